// round 11
// baseline (speedup 1.0000x reference)
#include <cuda_runtime.h>
#include <cuda_bf16.h>
#include <cstdint>
#include <math.h>

// Problem dims
#define B_   512
#define T_   512
#define IN_  128
#define H_   256
#define G3_  768   // 3*H
#define OUT_ 128

__device__ float g_ig[(size_t)B_ * T_ * G3_];     // ~805 MB  [B][T][3H]
__device__ float g_hfin[(size_t)B_ * H_];

typedef unsigned long long ull;

// ---------------- generic smem / cluster helpers ---------------------------
__device__ __forceinline__ uint32_t smem_u32(const void* p) {
    uint32_t a;
    asm("{ .reg .u64 t; cvta.to.shared.u64 t, %1; cvt.u32.u64 %0, t; }" : "=r"(a) : "l"(p));
    return a;
}
__device__ __forceinline__ uint32_t mapa_u32(uint32_t a, uint32_t rank) {
    uint32_t r;
    asm("mapa.shared::cluster.u32 %0, %1, %2;" : "=r"(r) : "r"(a), "r"(rank));
    return r;
}
__device__ __forceinline__ void stc_b32(uint32_t a, uint32_t v) {
    asm volatile("st.shared::cluster.u32 [%0], %1;" :: "r"(a), "r"(v) : "memory");
}
__device__ __forceinline__ void cluster_sync_() {
    asm volatile("barrier.cluster.arrive.aligned;" ::: "memory");
    asm volatile("barrier.cluster.wait.aligned;"   ::: "memory");
}
__device__ __forceinline__ void cluster_arrive_() {
    asm volatile("barrier.cluster.arrive.aligned;" ::: "memory");
}
__device__ __forceinline__ void cluster_wait_() {
    asm volatile("barrier.cluster.wait.aligned;"   ::: "memory");
}

// ---------------- mma.sync helpers (sm_80-era HMMA, valid on sm_100) -------
__device__ __forceinline__ void ldsm_x4(uint32_t* r, uint32_t addr) {
    asm volatile("ldmatrix.sync.aligned.m8n8.x4.shared.b16 {%0,%1,%2,%3}, [%4];"
                 : "=r"(r[0]), "=r"(r[1]), "=r"(r[2]), "=r"(r[3]) : "r"(addr));
}
__device__ __forceinline__ void ldsm_x2(uint32_t* r, uint32_t addr) {
    asm volatile("ldmatrix.sync.aligned.m8n8.x2.shared.b16 {%0,%1}, [%2];"
                 : "=r"(r[0]), "=r"(r[1]) : "r"(addr));
}
__device__ __forceinline__ void mma_bf16(float* d, const uint32_t* a, const uint32_t* b) {
    asm volatile(
        "mma.sync.aligned.m16n8k16.row.col.f32.bf16.bf16.f32 "
        "{%0,%1,%2,%3}, {%4,%5,%6,%7}, {%8,%9}, {%0,%1,%2,%3};"
        : "+f"(d[0]), "+f"(d[1]), "+f"(d[2]), "+f"(d[3])
        : "r"(a[0]), "r"(a[1]), "r"(a[2]), "r"(a[3]), "r"(b[0]), "r"(b[1]));
}

// bf16 hi/lo split of a float4 -> 4 packed bf16x2 (hi pair0, hi pair1, lo0, lo1)
__device__ __forceinline__ void split4(const float4 v,
                                       __nv_bfloat162& h0, __nv_bfloat162& h1,
                                       __nv_bfloat162& l0, __nv_bfloat162& l1) {
    h0 = __floats2bfloat162_rn(v.x, v.y);
    h1 = __floats2bfloat162_rn(v.z, v.w);
    l0 = __floats2bfloat162_rn(v.x - __bfloat162float(h0.x), v.y - __bfloat162float(h0.y));
    l1 = __floats2bfloat162_rn(v.z - __bfloat162float(h1.x), v.w - __bfloat162float(h1.y));
}

// ---------------------------------------------------------------------------
// Phase 1 (HMMA): ig = X @ W_ih^T + bias via bf16-split mma.sync.
// 128x64 tile, K=128 (2 chunks of 64). 8 warps = 4m x 2n, each warp 32x32:
// halves A-fragment redundancy vs 64x16 and lets B use paired-n ldmatrix.x4
// (8 ldsm / 24 HMMA per ks). 2 CTAs/SM.
// ---------------------------------------------------------------------------
#define P1_STR  72                      // bf16/row (64 + 8 pad); 144B ≡ 16 mod 128
#define AHI_OFF 0
#define ALO_OFF (128 * P1_STR * 2)      // 18432
#define BHI_OFF (2 * 128 * P1_STR * 2)  // 36864
#define BLO_OFF (BHI_OFF + 64 * P1_STR * 2)  // 46080
#define P1_SMEM_BYTES (BLO_OFF + 64 * P1_STR * 2)  // 55296

__global__ void __launch_bounds__(256, 2)
k_ih_mma(const float* __restrict__ X, const float* __restrict__ W,
         const float* __restrict__ bias)
{
    extern __shared__ char smc[];
    const uint32_t sb = smem_u32(smc);
    const int tid  = threadIdx.x;
    const int wid  = tid >> 5, lane = tid & 31;
    const int bn   = blockIdx.x;      // 0..11 (64-col blocks)
    const int bm   = blockIdx.y;      // 0..2047

    const int wm = wid & 3;           // 32-row band
    const int wn = wid >> 2;          // 32-col band

    // A x4: rows wm*32 + (lane&15) (+ mt*16), k-elem (lane>>4)*8 (+ ks*16)
    const uint32_t aHi0 = sb + AHI_OFF + 2u * ((wm * 32 + (lane & 15)) * P1_STR + (lane >> 4) * 8);
    const uint32_t aLo0 = aHi0 + ALO_OFF;
    // B paired x4: tiles np*2, np*2+1 -> rows wn*32 + ((lane>>4)&1)*8 + (lane&7) (+ np*16)
    const uint32_t bHi0 = sb + BHI_OFF + 2u * ((wn * 32 + ((lane >> 4) & 1) * 8 + (lane & 7)) * P1_STR
                                               + ((lane >> 3) & 1) * 8);
    const uint32_t bLo0 = bHi0 + (BLO_OFF - BHI_OFF);

    float acc[2][4][4];
#pragma unroll
    for (int mt = 0; mt < 2; mt++)
#pragma unroll
        for (int nt = 0; nt < 4; nt++)
#pragma unroll
            for (int e = 0; e < 4; e++) acc[mt][nt][e] = 0.f;

    for (int kk = 0; kk < 128; kk += 64) {
        if (kk) __syncthreads();
        // stage A (128 rows x 64 k): thread = (row, k-half)
        {
            const int row = tid >> 1;
            const int kp  = (tid & 1) * 32;
            const float* xs = X + ((size_t)(bm * 128 + row)) * 128 + kk + kp;
            __nv_bfloat16* ah = (__nv_bfloat16*)(smc + AHI_OFF) + row * P1_STR + kp;
            __nv_bfloat16* al = (__nv_bfloat16*)(smc + ALO_OFF) + row * P1_STR + kp;
#pragma unroll
            for (int q = 0; q < 8; q++) {
                __nv_bfloat162 h0, h1, l0, l1;
                split4(*(const float4*)(xs + q * 4), h0, h1, l0, l1);
                *(__nv_bfloat162*)(ah + q * 4)     = h0;
                *(__nv_bfloat162*)(ah + q * 4 + 2) = h1;
                *(__nv_bfloat162*)(al + q * 4)     = l0;
                *(__nv_bfloat162*)(al + q * 4 + 2) = l1;
            }
        }
        // stage B (64 rows x 64 k): thread = (row, k-quarter)
        {
            const int row = tid >> 2;
            const int kp  = (tid & 3) * 16;
            const float* ws = W + ((size_t)(bn * 64 + row)) * 128 + kk + kp;
            __nv_bfloat16* bh = (__nv_bfloat16*)(smc + BHI_OFF) + row * P1_STR + kp;
            __nv_bfloat16* bl = (__nv_bfloat16*)(smc + BLO_OFF) + row * P1_STR + kp;
#pragma unroll
            for (int q = 0; q < 4; q++) {
                __nv_bfloat162 h0, h1, l0, l1;
                split4(*(const float4*)(ws + q * 4), h0, h1, l0, l1);
                *(__nv_bfloat162*)(bh + q * 4)     = h0;
                *(__nv_bfloat162*)(bh + q * 4 + 2) = h1;
                *(__nv_bfloat162*)(bl + q * 4)     = l0;
                *(__nv_bfloat162*)(bl + q * 4 + 2) = l1;
            }
        }
        __syncthreads();

#pragma unroll
        for (int ks = 0; ks < 4; ks++) {
            const uint32_t ko = (uint32_t)(ks * 32);
            uint32_t ah[2][4], al[2][4];
#pragma unroll
            for (int mt = 0; mt < 2; mt++) {
                ldsm_x4(ah[mt], aHi0 + (uint32_t)(mt * 16 * P1_STR * 2) + ko);
                ldsm_x4(al[mt], aLo0 + (uint32_t)(mt * 16 * P1_STR * 2) + ko);
            }
            uint32_t bh[2][4], bl[2][4];     // [np]: {b0_t0,b1_t0,b0_t1,b1_t1}
#pragma unroll
            for (int np = 0; np < 2; np++) {
                ldsm_x4(bh[np], bHi0 + (uint32_t)(np * 16 * P1_STR * 2) + ko);
                ldsm_x4(bl[np], bLo0 + (uint32_t)(np * 16 * P1_STR * 2) + ko);
            }
            // chain-major: each acc revisited every 8 HMMAs
#pragma unroll
            for (int mt = 0; mt < 2; mt++)
#pragma unroll
                for (int nt = 0; nt < 4; nt++)
                    mma_bf16(acc[mt][nt], ah[mt], &bh[nt >> 1][(nt & 1) * 2]);
#pragma unroll
            for (int mt = 0; mt < 2; mt++)
#pragma unroll
                for (int nt = 0; nt < 4; nt++)
                    mma_bf16(acc[mt][nt], ah[mt], &bl[nt >> 1][(nt & 1) * 2]);
#pragma unroll
            for (int mt = 0; mt < 2; mt++)
#pragma unroll
                for (int nt = 0; nt < 4; nt++)
                    mma_bf16(acc[mt][nt], al[mt], &bh[nt >> 1][(nt & 1) * 2]);
        }
    }

    // epilogue
    const int grp = lane >> 2;
    const int qc  = (lane & 3) * 2;
#pragma unroll
    for (int mt = 0; mt < 2; mt++) {
        const int r0 = bm * 128 + wm * 32 + mt * 16 + grp;
#pragma unroll
        for (int nt = 0; nt < 4; nt++) {
            const int col = bn * 64 + wn * 32 + nt * 8 + qc;
            const float2 bb = *(const float2*)(bias + col);
            float* d0 = g_ig + (size_t)r0 * G3_ + col;
            float* d1 = d0 + (size_t)8 * G3_;
            *(float2*)d0 = make_float2(acc[mt][nt][0] + bb.x, acc[mt][nt][1] + bb.y);
            *(float2*)d1 = make_float2(acc[mt][nt][2] + bb.x, acc[mt][nt][3] + bb.y);
        }
    }
}

// ---------------------------------------------------------------------------
// Phase 2 (HMMA): GRU recurrence. Cluster of 4 CTAs; rank c owns 192 gate
// rows, W_hh chunk resident as bf16 hi/lo. Per step: D = h @ W^T (3 bf16
// chains), GRU cells in registers, h broadcast via DSMEM. This round:
// (a) W fragments via paired-n ldmatrix.x4 (6 ldsm/ks instead of 8);
// (b) split cluster barrier: arrive after phase A, wait after cell math,
//     hiding the first sync's latency behind phase B.
// ---------------------------------------------------------------------------
#define WSTR    264                 // bf16/row (256+8); 528B ≡ 16 mod 128
#define WLO_B   101376
#define HHI_B   202752
#define HLO_B   211200
#define D_B     219648
#define DSTR    200                 // floats
#define KR_SMEM_BYTES 232448

__device__ __forceinline__ float gru_cell(float igr, float igz, float ign,
                                          float ar, float az, float an,
                                          float bnv, float hp) {
    const float r = __fdividef(1.f, 1.f + __expf(-(igr + ar)));
    const float z = __fdividef(1.f, 1.f + __expf(-(igz + az)));
    const float a = ign + r * (an + bnv);
    const float n = __fdividef(2.f, 1.f + __expf(-2.f * a)) - 1.f;
    return n + z * (hp - n);
}

__global__ void __launch_bounds__(256, 1) __cluster_dims__(4, 1, 1)
k_rec_mma(const float* __restrict__ Whh, const float* __restrict__ bnb)
{
    extern __shared__ char smr[];
    const uint32_t sb = smem_u32(smr);
    const int tid = threadIdx.x;
    const int wid = tid >> 5, lane = tid & 31;
    const int c   = blockIdx.x & 3;   // cluster rank (unit chunk)
    const int cl  = blockIdx.x >> 2;  // cluster id: batch rows [cl*16, +16)

    // ---- stage W_hh chunk as bf16 hi/lo, local rows [r-units | z | n] ----
    if (tid < 192) {
        const int g = tid >> 6, u = tid & 63;
        const float* src = Whh + ((size_t)(g * 256 + c * 64 + u)) * 256;
        __nv_bfloat16* whi = (__nv_bfloat16*)(smr) + tid * WSTR;
        __nv_bfloat16* wlo = (__nv_bfloat16*)(smr + WLO_B) + tid * WSTR;
#pragma unroll 4
        for (int q = 0; q < 64; q++) {
            __nv_bfloat162 h0, h1, l0, l1;
            split4(*(const float4*)(src + q * 4), h0, h1, l0, l1);
            *(__nv_bfloat162*)(whi + q * 4)     = h0;
            *(__nv_bfloat162*)(whi + q * 4 + 2) = h1;
            *(__nv_bfloat162*)(wlo + q * 4)     = l0;
            *(__nv_bfloat162*)(wlo + q * 4 + 2) = l1;
        }
    }
    // zero h buffers (hi+lo, incl padding)
    for (int i = tid; i < 4224; i += 256) ((uint32_t*)(smr + HHI_B))[i] = 0;
    __syncthreads();
    cluster_sync_();

    // ---- phase-A fragment addresses (warp wid owns n-tiles tn0..tn0+2) ----
    const int tn0 = wid * 3;
    const uint32_t aHi = sb + HHI_B + 2u * ((lane & 15) * WSTR + (lane >> 4) * 8);
    const uint32_t aLo = aHi + (HLO_B - HHI_B);
    // paired x4 covers tiles tn0, tn0+1; x2 covers tile tn0+2
    const uint32_t bPair  = sb + 2u * ((tn0 * 8 + ((lane >> 4) & 1) * 8 + (lane & 7)) * WSTR
                                       + ((lane >> 3) & 1) * 8);
    const uint32_t bThird = sb + 2u * (((tn0 + 2) * 8 + (lane & 7)) * WSTR + ((lane >> 3) & 1) * 8);

    // ---- phase-B constants (warp == row-group: rows 2*wid, 2*wid+1) ------
    const int lu  = lane * 2;             // local units lu, lu+1
    const int gu  = c * 64 + lu;
    const int row0 = 2 * wid;
    const float2 bnv = *(const float2*)(bnb + gu);
    const float* ig0 = g_ig + ((size_t)(cl * 16 + row0)) * T_ * G3_ + gu;
    const float* ig1 = ig0 + (size_t)T_ * G3_;
    float* Dm = (float*)(smr + D_B);
    uint32_t pp[4];
#pragma unroll
    for (int r = 0; r < 4; r++) pp[r] = mapa_u32(sb, r);
    const uint32_t offH0 = HHI_B + 2u * (row0 * WSTR + gu);
    const uint32_t offH1 = HHI_B + 2u * ((row0 + 1) * WSTR + gu);
    float2 hp0 = make_float2(0.f, 0.f), hp1 = make_float2(0.f, 0.f);
    const int grp = lane >> 2, qc = (lane & 3) * 2;

    for (int t = 0; t < T_; t++) {
        // prefetch input gates for this thread's 2 rows x 2 units
        const float* p0 = ig0 + (size_t)t * G3_;
        const float* p1 = ig1 + (size_t)t * G3_;
        const float2 gr0 = *(const float2*)(p0);
        const float2 gz0 = *(const float2*)(p0 + 256);
        const float2 gn0 = *(const float2*)(p0 + 512);
        const float2 gr1 = *(const float2*)(p1);
        const float2 gz1 = *(const float2*)(p1 + 256);
        const float2 gn1 = *(const float2*)(p1 + 512);

        // ---- phase A: D = h @ W^T (3 bf16 chains) ----
        float a0[4] = {0.f, 0.f, 0.f, 0.f};
        float a1[4] = {0.f, 0.f, 0.f, 0.f};
        float a2[4] = {0.f, 0.f, 0.f, 0.f};
#pragma unroll
        for (int ks = 0; ks < 16; ks++) {
            const uint32_t ko = (uint32_t)(ks * 32);
            uint32_t ah[4], al[4];
            ldsm_x4(ah, aHi + ko);
            ldsm_x4(al, aLo + ko);
            uint32_t bph[4], bpl[4], bth[2], btl[2];
            ldsm_x4(bph, bPair + ko);
            ldsm_x4(bpl, bPair + WLO_B + ko);
            ldsm_x2(bth, bThird + ko);
            ldsm_x2(btl, bThird + WLO_B + ko);
            mma_bf16(a0, ah, &bph[0]); mma_bf16(a1, ah, &bph[2]); mma_bf16(a2, ah, bth);
            mma_bf16(a0, ah, &bpl[0]); mma_bf16(a1, ah, &bpl[2]); mma_bf16(a2, ah, btl);
            mma_bf16(a0, al, &bph[0]); mma_bf16(a1, al, &bph[2]); mma_bf16(a2, al, bth);
        }
        // stage D fragments (CTA-local slab)
        {
            const int col = tn0 * 8 + qc;
            *(float2*)(Dm + grp * DSTR + col)            = make_float2(a0[0], a0[1]);
            *(float2*)(Dm + (grp + 8) * DSTR + col)      = make_float2(a0[2], a0[3]);
            *(float2*)(Dm + grp * DSTR + col + 8)        = make_float2(a1[0], a1[1]);
            *(float2*)(Dm + (grp + 8) * DSTR + col + 8)  = make_float2(a1[2], a1[3]);
            *(float2*)(Dm + grp * DSTR + col + 16)       = make_float2(a2[0], a2[1]);
            *(float2*)(Dm + (grp + 8) * DSTR + col + 16) = make_float2(a2[2], a2[3]);
        }
        __syncthreads();    // Dm visible CTA-locally
        cluster_arrive_();  // signal: this CTA done reading h (phase A complete)

        // ---- phase B: GRU cells (overlaps the cluster barrier round-trip) --
        uint32_t wh0, wl0, wh1, wl1;
        {
            const float2 dr0 = *(const float2*)(Dm + row0 * DSTR + lu);
            const float2 dz0 = *(const float2*)(Dm + row0 * DSTR + 64 + lu);
            const float2 dn0 = *(const float2*)(Dm + row0 * DSTR + 128 + lu);
            const float2 dr1 = *(const float2*)(Dm + (row0 + 1) * DSTR + lu);
            const float2 dz1 = *(const float2*)(Dm + (row0 + 1) * DSTR + 64 + lu);
            const float2 dn1 = *(const float2*)(Dm + (row0 + 1) * DSTR + 128 + lu);

            const float h00 = gru_cell(gr0.x, gz0.x, gn0.x, dr0.x, dz0.x, dn0.x, bnv.x, hp0.x);
            const float h01 = gru_cell(gr0.y, gz0.y, gn0.y, dr0.y, dz0.y, dn0.y, bnv.y, hp0.y);
            const float h10 = gru_cell(gr1.x, gz1.x, gn1.x, dr1.x, dz1.x, dn1.x, bnv.x, hp1.x);
            const float h11 = gru_cell(gr1.y, gz1.y, gn1.y, dr1.y, dz1.y, dn1.y, bnv.y, hp1.y);
            hp0 = make_float2(h00, h01);
            hp1 = make_float2(h10, h11);

            __nv_bfloat162 hi0 = __floats2bfloat162_rn(h00, h01);
            __nv_bfloat162 lo0 = __floats2bfloat162_rn(h00 - __bfloat162float(hi0.x),
                                                       h01 - __bfloat162float(hi0.y));
            __nv_bfloat162 hi1 = __floats2bfloat162_rn(h10, h11);
            __nv_bfloat162 lo1 = __floats2bfloat162_rn(h10 - __bfloat162float(hi1.x),
                                                       h11 - __bfloat162float(hi1.y));
            wh0 = *reinterpret_cast<uint32_t*>(&hi0);
            wl0 = *reinterpret_cast<uint32_t*>(&lo0);
            wh1 = *reinterpret_cast<uint32_t*>(&hi1);
            wl1 = *reinterpret_cast<uint32_t*>(&lo1);
        }
        cluster_wait_();    // all CTAs finished reading h -> safe to overwrite

#pragma unroll
        for (int r = 0; r < 4; r++) {
            stc_b32(pp[r] + offH0, wh0);
            stc_b32(pp[r] + offH0 + (HLO_B - HHI_B), wl0);
            stc_b32(pp[r] + offH1, wh1);
            stc_b32(pp[r] + offH1 + (HLO_B - HHI_B), wl1);
        }
        cluster_sync_();    // h_{t+1} visible everywhere
    }

    // final h (in registers) -> g_hfin
    *(float2*)(g_hfin + (size_t)(cl * 16 + row0) * H_ + gu)     = hp0;
    *(float2*)(g_hfin + (size_t)(cl * 16 + row0 + 1) * H_ + gu) = hp1;
}

// ---------------------------------------------------------------------------
// Phase 3: out = h_final @ w_lin^T + bias_out   (512 x 128, trivial)
// ---------------------------------------------------------------------------
__global__ void __launch_bounds__(128) k_out(const float* __restrict__ wl,
                                             const float* __restrict__ bo,
                                             float* __restrict__ out)
{
    __shared__ float sh[256];
    const int b = blockIdx.x, o = threadIdx.x;
    sh[o]       = g_hfin[(size_t)b * H_ + o];
    sh[o + 128] = g_hfin[(size_t)b * H_ + o + 128];
    __syncthreads();

    float acc = bo[o];
    const float4* wp = (const float4*)(wl + (size_t)o * H_);
#pragma unroll 8
    for (int q = 0; q < 64; q++) {
        const float4 w = wp[q];
        const float4 h = *(const float4*)(sh + q * 4);
        acc += w.x * h.x + w.y * h.y + w.z * h.z + w.w * h.w;
    }
    out[(size_t)b * OUT_ + o] = acc;
}

// ---------------------------------------------------------------------------
extern "C" void kernel_launch(void* const* d_in, const int* in_sizes, int n_in,
                              void* d_out, int out_size)
{
    (void)in_sizes; (void)n_in; (void)out_size;
    const float* x   = (const float*)d_in[0];  // (B,T,IN)
    const float* wih = (const float*)d_in[1];  // (3H,IN)
    const float* whh = (const float*)d_in[2];  // (3H,H)
    const float* bg  = (const float*)d_in[3];  // (3H)
    const float* bnn = (const float*)d_in[4];  // (H)
    const float* wl  = (const float*)d_in[5];  // (OUT,H)
    const float* bo  = (const float*)d_in[6];  // (OUT)
    float* out = (float*)d_out;                // (B,OUT)

    cudaFuncSetAttribute(k_ih_mma,  cudaFuncAttributeMaxDynamicSharedMemorySize, P1_SMEM_BYTES);
    cudaFuncSetAttribute(k_rec_mma, cudaFuncAttributeMaxDynamicSharedMemorySize, KR_SMEM_BYTES);

    k_ih_mma<<<dim3(G3_ / 64, (B_ * T_) / 128), 256, P1_SMEM_BYTES>>>(x, wih, bg);
    k_rec_mma<<<128, 256, KR_SMEM_BYTES>>>(whh, bnn);
    k_out<<<B_, 128>>>(wl, bo, out);
}

// round 12
// speedup vs baseline: 1.0384x; 1.0384x over previous
#include <cuda_runtime.h>
#include <cuda_bf16.h>
#include <cstdint>
#include <math.h>

// Problem dims
#define B_   512
#define T_   512
#define IN_  128
#define H_   256
#define G3_  768   // 3*H
#define OUT_ 128

__device__ float g_ig[(size_t)B_ * T_ * G3_];     // ~805 MB  [B][T][3H]
__device__ float g_hfin[(size_t)B_ * H_];

typedef unsigned long long ull;

// ---------------- generic smem / cluster helpers ---------------------------
__device__ __forceinline__ uint32_t smem_u32(const void* p) {
    uint32_t a;
    asm("{ .reg .u64 t; cvta.to.shared.u64 t, %1; cvt.u32.u64 %0, t; }" : "=r"(a) : "l"(p));
    return a;
}
__device__ __forceinline__ uint32_t mapa_u32(uint32_t a, uint32_t rank) {
    uint32_t r;
    asm("mapa.shared::cluster.u32 %0, %1, %2;" : "=r"(r) : "r"(a), "r"(rank));
    return r;
}
__device__ __forceinline__ void stc_b32(uint32_t a, uint32_t v) {
    asm volatile("st.shared::cluster.u32 [%0], %1;" :: "r"(a), "r"(v) : "memory");
}
__device__ __forceinline__ void cluster_sync_() {
    asm volatile("barrier.cluster.arrive.aligned;" ::: "memory");
    asm volatile("barrier.cluster.wait.aligned;"   ::: "memory");
}

// ---------------- mma.sync helpers (sm_80-era HMMA, valid on sm_100) -------
__device__ __forceinline__ void ldsm_x4(uint32_t* r, uint32_t addr) {
    asm volatile("ldmatrix.sync.aligned.m8n8.x4.shared.b16 {%0,%1,%2,%3}, [%4];"
                 : "=r"(r[0]), "=r"(r[1]), "=r"(r[2]), "=r"(r[3]) : "r"(addr));
}
__device__ __forceinline__ void ldsm_x2(uint32_t* r, uint32_t addr) {
    asm volatile("ldmatrix.sync.aligned.m8n8.x2.shared.b16 {%0,%1}, [%2];"
                 : "=r"(r[0]), "=r"(r[1]) : "r"(addr));
}
__device__ __forceinline__ void mma_bf16(float* d, const uint32_t* a, const uint32_t* b) {
    asm volatile(
        "mma.sync.aligned.m16n8k16.row.col.f32.bf16.bf16.f32 "
        "{%0,%1,%2,%3}, {%4,%5,%6,%7}, {%8,%9}, {%0,%1,%2,%3};"
        : "+f"(d[0]), "+f"(d[1]), "+f"(d[2]), "+f"(d[3])
        : "r"(a[0]), "r"(a[1]), "r"(a[2]), "r"(a[3]), "r"(b[0]), "r"(b[1]));
}

// bf16 hi/lo split of a float4 -> 4 packed bf16x2 (hi pair0, hi pair1, lo0, lo1)
__device__ __forceinline__ void split4(const float4 v,
                                       __nv_bfloat162& h0, __nv_bfloat162& h1,
                                       __nv_bfloat162& l0, __nv_bfloat162& l1) {
    h0 = __floats2bfloat162_rn(v.x, v.y);
    h1 = __floats2bfloat162_rn(v.z, v.w);
    l0 = __floats2bfloat162_rn(v.x - __bfloat162float(h0.x), v.y - __bfloat162float(h0.y));
    l1 = __floats2bfloat162_rn(v.z - __bfloat162float(h1.x), v.w - __bfloat162float(h1.y));
}

// ---------------------------------------------------------------------------
// Phase 1 (HMMA): ig = X @ W_ih^T + bias via bf16-split mma.sync.
// 128x128 CTA tile, K=128 (2 chunks of 64). 8 warps = 4m x 2n, each warp
// 32x64: ldsm:HMMA ratio 12:48 (vs 8:24 before) on an L1-bound kernel.
// smem 73728 B -> 2 CTAs/SM.
// ---------------------------------------------------------------------------
#define P1_STR  72                      // bf16/row (64 + 8 pad)
#define AHI_OFF 0
#define ALO_OFF (128 * P1_STR * 2)      // 18432
#define BHI_OFF (2 * 128 * P1_STR * 2)  // 36864
#define BLO_OFF (BHI_OFF + 128 * P1_STR * 2)  // 55296
#define P1_SMEM_BYTES (BLO_OFF + 128 * P1_STR * 2)  // 73728

__global__ void __launch_bounds__(256, 2)
k_ih_mma(const float* __restrict__ X, const float* __restrict__ W,
         const float* __restrict__ bias)
{
    extern __shared__ char smc[];
    const uint32_t sb = smem_u32(smc);
    const int tid  = threadIdx.x;
    const int wid  = tid >> 5, lane = tid & 31;
    const int bn   = blockIdx.x;      // 0..5 (128-col blocks)
    const int bm   = blockIdx.y;      // 0..2047

    const int wm = wid & 3;           // 32-row band
    const int wn = wid >> 2;          // 64-col band

    // A x4: rows wm*32 + (lane&15) (+ mt*16), k-elem (lane>>4)*8 (+ ks*16)
    const uint32_t aHi0 = sb + AHI_OFF + 2u * ((wm * 32 + (lane & 15)) * P1_STR + (lane >> 4) * 8);
    const uint32_t aLo0 = aHi0 + ALO_OFF;
    // B paired x4: tiles 2np,2np+1 -> rows wn*64 + ((lane>>4)&1)*8 + (lane&7) (+ np*16)
    const uint32_t bHi0 = sb + BHI_OFF + 2u * ((wn * 64 + ((lane >> 4) & 1) * 8 + (lane & 7)) * P1_STR
                                               + ((lane >> 3) & 1) * 8);
    const uint32_t bLo0 = bHi0 + (BLO_OFF - BHI_OFF);

    float acc[2][8][4];
#pragma unroll
    for (int mt = 0; mt < 2; mt++)
#pragma unroll
        for (int nt = 0; nt < 8; nt++)
#pragma unroll
            for (int e = 0; e < 4; e++) acc[mt][nt][e] = 0.f;

    for (int kk = 0; kk < 128; kk += 64) {
        if (kk) __syncthreads();
        // stage A (128 rows x 64 k) and B (128 rows x 64 k): thread = (row, k-half)
        {
            const int row = tid >> 1;
            const int kp  = (tid & 1) * 32;
            const float* xs = X + ((size_t)(bm * 128 + row)) * 128 + kk + kp;
            const float* ws = W + ((size_t)(bn * 128 + row)) * 128 + kk + kp;
            __nv_bfloat16* ah = (__nv_bfloat16*)(smc + AHI_OFF) + row * P1_STR + kp;
            __nv_bfloat16* al = (__nv_bfloat16*)(smc + ALO_OFF) + row * P1_STR + kp;
            __nv_bfloat16* bh = (__nv_bfloat16*)(smc + BHI_OFF) + row * P1_STR + kp;
            __nv_bfloat16* bl = (__nv_bfloat16*)(smc + BLO_OFF) + row * P1_STR + kp;
#pragma unroll
            for (int q = 0; q < 8; q++) {
                __nv_bfloat162 h0, h1, l0, l1;
                split4(*(const float4*)(xs + q * 4), h0, h1, l0, l1);
                *(__nv_bfloat162*)(ah + q * 4)     = h0;
                *(__nv_bfloat162*)(ah + q * 4 + 2) = h1;
                *(__nv_bfloat162*)(al + q * 4)     = l0;
                *(__nv_bfloat162*)(al + q * 4 + 2) = l1;
                split4(*(const float4*)(ws + q * 4), h0, h1, l0, l1);
                *(__nv_bfloat162*)(bh + q * 4)     = h0;
                *(__nv_bfloat162*)(bh + q * 4 + 2) = h1;
                *(__nv_bfloat162*)(bl + q * 4)     = l0;
                *(__nv_bfloat162*)(bl + q * 4 + 2) = l1;
            }
        }
        __syncthreads();

#pragma unroll
        for (int ks = 0; ks < 4; ks++) {
            const uint32_t ko = (uint32_t)(ks * 32);
            uint32_t ah[2][4], bh[4][4];
#pragma unroll
            for (int mt = 0; mt < 2; mt++)
                ldsm_x4(ah[mt], aHi0 + (uint32_t)(mt * 16 * P1_STR * 2) + ko);
#pragma unroll
            for (int np = 0; np < 4; np++)
                ldsm_x4(bh[np], bHi0 + (uint32_t)(np * 16 * P1_STR * 2) + ko);
            // chain 1: hi*hi
#pragma unroll
            for (int mt = 0; mt < 2; mt++)
#pragma unroll
                for (int nt = 0; nt < 8; nt++)
                    mma_bf16(acc[mt][nt], ah[mt], &bh[nt >> 1][(nt & 1) * 2]);
            // chain 2: hi*lo
            {
                uint32_t bl[4][4];
#pragma unroll
                for (int np = 0; np < 4; np++)
                    ldsm_x4(bl[np], bLo0 + (uint32_t)(np * 16 * P1_STR * 2) + ko);
#pragma unroll
                for (int mt = 0; mt < 2; mt++)
#pragma unroll
                    for (int nt = 0; nt < 8; nt++)
                        mma_bf16(acc[mt][nt], ah[mt], &bl[nt >> 1][(nt & 1) * 2]);
            }
            // chain 3: lo*hi
            {
                uint32_t al[2][4];
#pragma unroll
                for (int mt = 0; mt < 2; mt++)
                    ldsm_x4(al[mt], aLo0 + (uint32_t)(mt * 16 * P1_STR * 2) + ko);
#pragma unroll
                for (int mt = 0; mt < 2; mt++)
#pragma unroll
                    for (int nt = 0; nt < 8; nt++)
                        mma_bf16(acc[mt][nt], al[mt], &bh[nt >> 1][(nt & 1) * 2]);
            }
        }
    }

    // epilogue
    const int grp = lane >> 2;
    const int qc  = (lane & 3) * 2;
#pragma unroll
    for (int mt = 0; mt < 2; mt++) {
        const int r0 = bm * 128 + wm * 32 + mt * 16 + grp;
#pragma unroll
        for (int nt = 0; nt < 8; nt++) {
            const int col = bn * 128 + wn * 64 + nt * 8 + qc;
            const float2 bb = *(const float2*)(bias + col);
            float* d0 = g_ig + (size_t)r0 * G3_ + col;
            float* d1 = d0 + (size_t)8 * G3_;
            *(float2*)d0 = make_float2(acc[mt][nt][0] + bb.x, acc[mt][nt][1] + bb.y);
            *(float2*)d1 = make_float2(acc[mt][nt][2] + bb.x, acc[mt][nt][3] + bb.y);
        }
    }
}

// ---------------------------------------------------------------------------
// Phase 2 (HMMA): GRU recurrence. R10 barrier structure (proven 1.62 ms):
// stage D -> cluster_sync -> phase B -> DSMEM stores -> cluster_sync.
// Keeps R11's paired-x4 W fragment loads (6 ldsm/ks).
// ---------------------------------------------------------------------------
#define WSTR    264                 // bf16/row (256+8)
#define WLO_B   101376
#define HHI_B   202752
#define HLO_B   211200
#define D_B     219648
#define DSTR    200                 // floats
#define KR_SMEM_BYTES 232448

__device__ __forceinline__ float gru_cell(float igr, float igz, float ign,
                                          float ar, float az, float an,
                                          float bnv, float hp) {
    const float r = __fdividef(1.f, 1.f + __expf(-(igr + ar)));
    const float z = __fdividef(1.f, 1.f + __expf(-(igz + az)));
    const float a = ign + r * (an + bnv);
    const float n = __fdividef(2.f, 1.f + __expf(-2.f * a)) - 1.f;
    return n + z * (hp - n);
}

__global__ void __launch_bounds__(256, 1) __cluster_dims__(4, 1, 1)
k_rec_mma(const float* __restrict__ Whh, const float* __restrict__ bnb)
{
    extern __shared__ char smr[];
    const uint32_t sb = smem_u32(smr);
    const int tid = threadIdx.x;
    const int wid = tid >> 5, lane = tid & 31;
    const int c   = blockIdx.x & 3;   // cluster rank (unit chunk)
    const int cl  = blockIdx.x >> 2;  // cluster id: batch rows [cl*16, +16)

    // ---- stage W_hh chunk as bf16 hi/lo, local rows [r-units | z | n] ----
    if (tid < 192) {
        const int g = tid >> 6, u = tid & 63;
        const float* src = Whh + ((size_t)(g * 256 + c * 64 + u)) * 256;
        __nv_bfloat16* whi = (__nv_bfloat16*)(smr) + tid * WSTR;
        __nv_bfloat16* wlo = (__nv_bfloat16*)(smr + WLO_B) + tid * WSTR;
#pragma unroll 4
        for (int q = 0; q < 64; q++) {
            __nv_bfloat162 h0, h1, l0, l1;
            split4(*(const float4*)(src + q * 4), h0, h1, l0, l1);
            *(__nv_bfloat162*)(whi + q * 4)     = h0;
            *(__nv_bfloat162*)(whi + q * 4 + 2) = h1;
            *(__nv_bfloat162*)(wlo + q * 4)     = l0;
            *(__nv_bfloat162*)(wlo + q * 4 + 2) = l1;
        }
    }
    // zero h buffers (hi+lo, incl padding)
    for (int i = tid; i < 4224; i += 256) ((uint32_t*)(smr + HHI_B))[i] = 0;
    __syncthreads();
    cluster_sync_();

    // ---- phase-A fragment addresses (warp wid owns n-tiles tn0..tn0+2) ----
    const int tn0 = wid * 3;
    const uint32_t aHi = sb + HHI_B + 2u * ((lane & 15) * WSTR + (lane >> 4) * 8);
    const uint32_t aLo = aHi + (HLO_B - HHI_B);
    // paired x4 covers tiles tn0, tn0+1; x2 covers tile tn0+2
    const uint32_t bPair  = sb + 2u * ((tn0 * 8 + ((lane >> 4) & 1) * 8 + (lane & 7)) * WSTR
                                       + ((lane >> 3) & 1) * 8);
    const uint32_t bThird = sb + 2u * (((tn0 + 2) * 8 + (lane & 7)) * WSTR + ((lane >> 3) & 1) * 8);

    // ---- phase-B constants (warp == row-group: rows 2*wid, 2*wid+1) ------
    const int lu  = lane * 2;             // local units lu, lu+1
    const int gu  = c * 64 + lu;
    const int row0 = 2 * wid;
    const float2 bnv = *(const float2*)(bnb + gu);
    const float* ig0 = g_ig + ((size_t)(cl * 16 + row0)) * T_ * G3_ + gu;
    const float* ig1 = ig0 + (size_t)T_ * G3_;
    float* Dm = (float*)(smr + D_B);
    uint32_t pp[4];
#pragma unroll
    for (int r = 0; r < 4; r++) pp[r] = mapa_u32(sb, r);
    const uint32_t offH0 = HHI_B + 2u * (row0 * WSTR + gu);
    const uint32_t offH1 = HHI_B + 2u * ((row0 + 1) * WSTR + gu);
    float2 hp0 = make_float2(0.f, 0.f), hp1 = make_float2(0.f, 0.f);
    const int grp = lane >> 2, qc = (lane & 3) * 2;

    for (int t = 0; t < T_; t++) {
        // prefetch input gates for this thread's 2 rows x 2 units
        const float* p0 = ig0 + (size_t)t * G3_;
        const float* p1 = ig1 + (size_t)t * G3_;
        const float2 gr0 = *(const float2*)(p0);
        const float2 gz0 = *(const float2*)(p0 + 256);
        const float2 gn0 = *(const float2*)(p0 + 512);
        const float2 gr1 = *(const float2*)(p1);
        const float2 gz1 = *(const float2*)(p1 + 256);
        const float2 gn1 = *(const float2*)(p1 + 512);

        // ---- phase A: D = h @ W^T (3 bf16 chains) ----
        float a0[4] = {0.f, 0.f, 0.f, 0.f};
        float a1[4] = {0.f, 0.f, 0.f, 0.f};
        float a2[4] = {0.f, 0.f, 0.f, 0.f};
#pragma unroll
        for (int ks = 0; ks < 16; ks++) {
            const uint32_t ko = (uint32_t)(ks * 32);
            uint32_t ah[4], al[4];
            ldsm_x4(ah, aHi + ko);
            ldsm_x4(al, aLo + ko);
            uint32_t bph[4], bpl[4], bth[2], btl[2];
            ldsm_x4(bph, bPair + ko);
            ldsm_x4(bpl, bPair + WLO_B + ko);
            ldsm_x2(bth, bThird + ko);
            ldsm_x2(btl, bThird + WLO_B + ko);
            mma_bf16(a0, ah, &bph[0]); mma_bf16(a1, ah, &bph[2]); mma_bf16(a2, ah, bth);
            mma_bf16(a0, ah, &bpl[0]); mma_bf16(a1, ah, &bpl[2]); mma_bf16(a2, ah, btl);
            mma_bf16(a0, al, &bph[0]); mma_bf16(a1, al, &bph[2]); mma_bf16(a2, al, bth);
        }
        // stage D fragments
        {
            const int col = tn0 * 8 + qc;
            *(float2*)(Dm + grp * DSTR + col)            = make_float2(a0[0], a0[1]);
            *(float2*)(Dm + (grp + 8) * DSTR + col)      = make_float2(a0[2], a0[3]);
            *(float2*)(Dm + grp * DSTR + col + 8)        = make_float2(a1[0], a1[1]);
            *(float2*)(Dm + (grp + 8) * DSTR + col + 8)  = make_float2(a1[2], a1[3]);
            *(float2*)(Dm + grp * DSTR + col + 16)       = make_float2(a2[0], a2[1]);
            *(float2*)(Dm + (grp + 8) * DSTR + col + 16) = make_float2(a2[2], a2[3]);
        }
        cluster_sync_();   // D visible (incl. CTA-local); all ranks done reading h

        // ---- phase B: GRU cells + cluster-wide h update ----
        {
            const float2 dr0 = *(const float2*)(Dm + row0 * DSTR + lu);
            const float2 dz0 = *(const float2*)(Dm + row0 * DSTR + 64 + lu);
            const float2 dn0 = *(const float2*)(Dm + row0 * DSTR + 128 + lu);
            const float2 dr1 = *(const float2*)(Dm + (row0 + 1) * DSTR + lu);
            const float2 dz1 = *(const float2*)(Dm + (row0 + 1) * DSTR + 64 + lu);
            const float2 dn1 = *(const float2*)(Dm + (row0 + 1) * DSTR + 128 + lu);

            const float h00 = gru_cell(gr0.x, gz0.x, gn0.x, dr0.x, dz0.x, dn0.x, bnv.x, hp0.x);
            const float h01 = gru_cell(gr0.y, gz0.y, gn0.y, dr0.y, dz0.y, dn0.y, bnv.y, hp0.y);
            const float h10 = gru_cell(gr1.x, gz1.x, gn1.x, dr1.x, dz1.x, dn1.x, bnv.x, hp1.x);
            const float h11 = gru_cell(gr1.y, gz1.y, gn1.y, dr1.y, dz1.y, dn1.y, bnv.y, hp1.y);
            hp0 = make_float2(h00, h01);
            hp1 = make_float2(h10, h11);

            __nv_bfloat162 hi0 = __floats2bfloat162_rn(h00, h01);
            __nv_bfloat162 lo0 = __floats2bfloat162_rn(h00 - __bfloat162float(hi0.x),
                                                       h01 - __bfloat162float(hi0.y));
            __nv_bfloat162 hi1 = __floats2bfloat162_rn(h10, h11);
            __nv_bfloat162 lo1 = __floats2bfloat162_rn(h10 - __bfloat162float(hi1.x),
                                                       h11 - __bfloat162float(hi1.y));
            const uint32_t wh0 = *reinterpret_cast<uint32_t*>(&hi0);
            const uint32_t wl0 = *reinterpret_cast<uint32_t*>(&lo0);
            const uint32_t wh1 = *reinterpret_cast<uint32_t*>(&hi1);
            const uint32_t wl1 = *reinterpret_cast<uint32_t*>(&lo1);
#pragma unroll
            for (int r = 0; r < 4; r++) {
                stc_b32(pp[r] + offH0, wh0);
                stc_b32(pp[r] + offH0 + (HLO_B - HHI_B), wl0);
                stc_b32(pp[r] + offH1, wh1);
                stc_b32(pp[r] + offH1 + (HLO_B - HHI_B), wl1);
            }
        }
        cluster_sync_();   // h_{t+1} visible everywhere
    }

    // final h (in registers) -> g_hfin
    *(float2*)(g_hfin + (size_t)(cl * 16 + row0) * H_ + gu)     = hp0;
    *(float2*)(g_hfin + (size_t)(cl * 16 + row0 + 1) * H_ + gu) = hp1;
}

// ---------------------------------------------------------------------------
// Phase 3: out = h_final @ w_lin^T + bias_out   (512 x 128, trivial)
// ---------------------------------------------------------------------------
__global__ void __launch_bounds__(128) k_out(const float* __restrict__ wl,
                                             const float* __restrict__ bo,
                                             float* __restrict__ out)
{
    __shared__ float sh[256];
    const int b = blockIdx.x, o = threadIdx.x;
    sh[o]       = g_hfin[(size_t)b * H_ + o];
    sh[o + 128] = g_hfin[(size_t)b * H_ + o + 128];
    __syncthreads();

    float acc = bo[o];
    const float4* wp = (const float4*)(wl + (size_t)o * H_);
#pragma unroll 8
    for (int q = 0; q < 64; q++) {
        const float4 w = wp[q];
        const float4 h = *(const float4*)(sh + q * 4);
        acc += w.x * h.x + w.y * h.y + w.z * h.z + w.w * h.w;
    }
    out[(size_t)b * OUT_ + o] = acc;
}

// ---------------------------------------------------------------------------
extern "C" void kernel_launch(void* const* d_in, const int* in_sizes, int n_in,
                              void* d_out, int out_size)
{
    (void)in_sizes; (void)n_in; (void)out_size;
    const float* x   = (const float*)d_in[0];  // (B,T,IN)
    const float* wih = (const float*)d_in[1];  // (3H,IN)
    const float* whh = (const float*)d_in[2];  // (3H,H)
    const float* bg  = (const float*)d_in[3];  // (3H)
    const float* bnn = (const float*)d_in[4];  // (H)
    const float* wl  = (const float*)d_in[5];  // (OUT,H)
    const float* bo  = (const float*)d_in[6];  // (OUT)
    float* out = (float*)d_out;                // (B,OUT)

    cudaFuncSetAttribute(k_ih_mma,  cudaFuncAttributeMaxDynamicSharedMemorySize, P1_SMEM_BYTES);
    cudaFuncSetAttribute(k_rec_mma, cudaFuncAttributeMaxDynamicSharedMemorySize, KR_SMEM_BYTES);

    k_ih_mma<<<dim3(G3_ / 128, (B_ * T_) / 128), 256, P1_SMEM_BYTES>>>(x, wih, bg);
    k_rec_mma<<<128, 256, KR_SMEM_BYTES>>>(whh, bnn);
    k_out<<<B_, 128>>>(wl, bo, out);
}

// round 13
// speedup vs baseline: 1.1305x; 1.0887x over previous
#include <cuda_runtime.h>
#include <cuda_bf16.h>
#include <cstdint>
#include <math.h>

// Problem dims
#define B_   512
#define T_   512
#define IN_  128
#define H_   256
#define G3_  768   // 3*H
#define OUT_ 128

__device__ float g_ig[(size_t)B_ * T_ * G3_];     // ~805 MB  [B][T][3H]
__device__ float g_hfin[(size_t)B_ * H_];

typedef unsigned long long ull;

// ---------------- generic smem / cluster helpers ---------------------------
__device__ __forceinline__ uint32_t smem_u32(const void* p) {
    uint32_t a;
    asm("{ .reg .u64 t; cvta.to.shared.u64 t, %1; cvt.u32.u64 %0, t; }" : "=r"(a) : "l"(p));
    return a;
}
__device__ __forceinline__ uint32_t mapa_u32(uint32_t a, uint32_t rank) {
    uint32_t r;
    asm("mapa.shared::cluster.u32 %0, %1, %2;" : "=r"(r) : "r"(a), "r"(rank));
    return r;
}
__device__ __forceinline__ void stc_b32(uint32_t a, uint32_t v) {
    asm volatile("st.shared::cluster.u32 [%0], %1;" :: "r"(a), "r"(v) : "memory");
}
__device__ __forceinline__ void cluster_sync_() {
    asm volatile("barrier.cluster.arrive.aligned;" ::: "memory");
    asm volatile("barrier.cluster.wait.aligned;"   ::: "memory");
}

// ---------------- mma.sync helpers (sm_80-era HMMA, valid on sm_100) -------
__device__ __forceinline__ void ldsm_x4(uint32_t* r, uint32_t addr) {
    asm volatile("ldmatrix.sync.aligned.m8n8.x4.shared.b16 {%0,%1,%2,%3}, [%4];"
                 : "=r"(r[0]), "=r"(r[1]), "=r"(r[2]), "=r"(r[3]) : "r"(addr));
}
__device__ __forceinline__ void ldsm_x2(uint32_t* r, uint32_t addr) {
    asm volatile("ldmatrix.sync.aligned.m8n8.x2.shared.b16 {%0,%1}, [%2];"
                 : "=r"(r[0]), "=r"(r[1]) : "r"(addr));
}
__device__ __forceinline__ void mma_bf16(float* d, const uint32_t* a, const uint32_t* b) {
    asm volatile(
        "mma.sync.aligned.m16n8k16.row.col.f32.bf16.bf16.f32 "
        "{%0,%1,%2,%3}, {%4,%5,%6,%7}, {%8,%9}, {%0,%1,%2,%3};"
        : "+f"(d[0]), "+f"(d[1]), "+f"(d[2]), "+f"(d[3])
        : "r"(a[0]), "r"(a[1]), "r"(a[2]), "r"(a[3]), "r"(b[0]), "r"(b[1]));
}

// bf16 hi/lo split of a float4 -> 4 packed bf16x2 (hi pair0, hi pair1, lo0, lo1)
__device__ __forceinline__ void split4(const float4 v,
                                       __nv_bfloat162& h0, __nv_bfloat162& h1,
                                       __nv_bfloat162& l0, __nv_bfloat162& l1) {
    h0 = __floats2bfloat162_rn(v.x, v.y);
    h1 = __floats2bfloat162_rn(v.z, v.w);
    l0 = __floats2bfloat162_rn(v.x - __bfloat162float(h0.x), v.y - __bfloat162float(h0.y));
    l1 = __floats2bfloat162_rn(v.z - __bfloat162float(h1.x), v.w - __bfloat162float(h1.y));
}

// ---------------------------------------------------------------------------
// Phase 1 (HMMA): ig = X @ W_ih^T + bias via bf16-split mma.sync.
// 128x128 CTA tile, K=128 (2 chunks of 64). 8 warps = 4m x 2n, each warp
// 32x64 (proven 815 us in R12). smem 73728 B -> 2 CTAs/SM.
// ---------------------------------------------------------------------------
#define P1_STR  72                      // bf16/row (64 + 8 pad)
#define AHI_OFF 0
#define ALO_OFF (128 * P1_STR * 2)      // 18432
#define BHI_OFF (2 * 128 * P1_STR * 2)  // 36864
#define BLO_OFF (BHI_OFF + 128 * P1_STR * 2)  // 55296
#define P1_SMEM_BYTES (BLO_OFF + 128 * P1_STR * 2)  // 73728

__global__ void __launch_bounds__(256, 2)
k_ih_mma(const float* __restrict__ X, const float* __restrict__ W,
         const float* __restrict__ bias)
{
    extern __shared__ char smc[];
    const uint32_t sb = smem_u32(smc);
    const int tid  = threadIdx.x;
    const int wid  = tid >> 5, lane = tid & 31;
    const int bn   = blockIdx.x;      // 0..5 (128-col blocks)
    const int bm   = blockIdx.y;      // 0..2047

    const int wm = wid & 3;           // 32-row band
    const int wn = wid >> 2;          // 64-col band

    // A x4: rows wm*32 + (lane&15) (+ mt*16), k-elem (lane>>4)*8 (+ ks*16)
    const uint32_t aHi0 = sb + AHI_OFF + 2u * ((wm * 32 + (lane & 15)) * P1_STR + (lane >> 4) * 8);
    const uint32_t aLo0 = aHi0 + ALO_OFF;
    // B paired x4: tiles 2np,2np+1 -> rows wn*64 + ((lane>>4)&1)*8 + (lane&7) (+ np*16)
    const uint32_t bHi0 = sb + BHI_OFF + 2u * ((wn * 64 + ((lane >> 4) & 1) * 8 + (lane & 7)) * P1_STR
                                               + ((lane >> 3) & 1) * 8);
    const uint32_t bLo0 = bHi0 + (BLO_OFF - BHI_OFF);

    float acc[2][8][4];
#pragma unroll
    for (int mt = 0; mt < 2; mt++)
#pragma unroll
        for (int nt = 0; nt < 8; nt++)
#pragma unroll
            for (int e = 0; e < 4; e++) acc[mt][nt][e] = 0.f;

    for (int kk = 0; kk < 128; kk += 64) {
        if (kk) __syncthreads();
        // stage A (128 rows x 64 k) and B (128 rows x 64 k): thread = (row, k-half)
        {
            const int row = tid >> 1;
            const int kp  = (tid & 1) * 32;
            const float* xs = X + ((size_t)(bm * 128 + row)) * 128 + kk + kp;
            const float* ws = W + ((size_t)(bn * 128 + row)) * 128 + kk + kp;
            __nv_bfloat16* ah = (__nv_bfloat16*)(smc + AHI_OFF) + row * P1_STR + kp;
            __nv_bfloat16* al = (__nv_bfloat16*)(smc + ALO_OFF) + row * P1_STR + kp;
            __nv_bfloat16* bh = (__nv_bfloat16*)(smc + BHI_OFF) + row * P1_STR + kp;
            __nv_bfloat16* bl = (__nv_bfloat16*)(smc + BLO_OFF) + row * P1_STR + kp;
#pragma unroll
            for (int q = 0; q < 8; q++) {
                __nv_bfloat162 h0, h1, l0, l1;
                split4(*(const float4*)(xs + q * 4), h0, h1, l0, l1);
                *(__nv_bfloat162*)(ah + q * 4)     = h0;
                *(__nv_bfloat162*)(ah + q * 4 + 2) = h1;
                *(__nv_bfloat162*)(al + q * 4)     = l0;
                *(__nv_bfloat162*)(al + q * 4 + 2) = l1;
                split4(*(const float4*)(ws + q * 4), h0, h1, l0, l1);
                *(__nv_bfloat162*)(bh + q * 4)     = h0;
                *(__nv_bfloat162*)(bh + q * 4 + 2) = h1;
                *(__nv_bfloat162*)(bl + q * 4)     = l0;
                *(__nv_bfloat162*)(bl + q * 4 + 2) = l1;
            }
        }
        __syncthreads();

#pragma unroll
        for (int ks = 0; ks < 4; ks++) {
            const uint32_t ko = (uint32_t)(ks * 32);
            uint32_t ah[2][4], bh[4][4];
#pragma unroll
            for (int mt = 0; mt < 2; mt++)
                ldsm_x4(ah[mt], aHi0 + (uint32_t)(mt * 16 * P1_STR * 2) + ko);
#pragma unroll
            for (int np = 0; np < 4; np++)
                ldsm_x4(bh[np], bHi0 + (uint32_t)(np * 16 * P1_STR * 2) + ko);
            // chain 1: hi*hi
#pragma unroll
            for (int mt = 0; mt < 2; mt++)
#pragma unroll
                for (int nt = 0; nt < 8; nt++)
                    mma_bf16(acc[mt][nt], ah[mt], &bh[nt >> 1][(nt & 1) * 2]);
            // chain 2: hi*lo
            {
                uint32_t bl[4][4];
#pragma unroll
                for (int np = 0; np < 4; np++)
                    ldsm_x4(bl[np], bLo0 + (uint32_t)(np * 16 * P1_STR * 2) + ko);
#pragma unroll
                for (int mt = 0; mt < 2; mt++)
#pragma unroll
                    for (int nt = 0; nt < 8; nt++)
                        mma_bf16(acc[mt][nt], ah[mt], &bl[nt >> 1][(nt & 1) * 2]);
            }
            // chain 3: lo*hi
            {
                uint32_t al[2][4];
#pragma unroll
                for (int mt = 0; mt < 2; mt++)
                    ldsm_x4(al[mt], aLo0 + (uint32_t)(mt * 16 * P1_STR * 2) + ko);
#pragma unroll
                for (int mt = 0; mt < 2; mt++)
#pragma unroll
                    for (int nt = 0; nt < 8; nt++)
                        mma_bf16(acc[mt][nt], al[mt], &bh[nt >> 1][(nt & 1) * 2]);
            }
        }
    }

    // epilogue
    const int grp = lane >> 2;
    const int qc  = (lane & 3) * 2;
#pragma unroll
    for (int mt = 0; mt < 2; mt++) {
        const int r0 = bm * 128 + wm * 32 + mt * 16 + grp;
#pragma unroll
        for (int nt = 0; nt < 8; nt++) {
            const int col = bn * 128 + wn * 64 + nt * 8 + qc;
            const float2 bb = *(const float2*)(bias + col);
            float* d0 = g_ig + (size_t)r0 * G3_ + col;
            float* d1 = d0 + (size_t)8 * G3_;
            *(float2*)d0 = make_float2(acc[mt][nt][0] + bb.x, acc[mt][nt][1] + bb.y);
            *(float2*)d1 = make_float2(acc[mt][nt][2] + bb.x, acc[mt][nt][3] + bb.y);
        }
    }
}

// ---------------------------------------------------------------------------
// Phase 2 (HMMA): GRU recurrence — EXACT R10 structure (proven 1.62 ms):
// per-tile ldsm_x2 W fragment loads (small live sets), stage D ->
// cluster_sync -> phase B -> DSMEM stores -> cluster_sync.
// ---------------------------------------------------------------------------
#define WSTR    264                 // bf16/row (256+8)
#define WLO_B   101376
#define HHI_B   202752
#define HLO_B   211200
#define D_B     219648
#define DSTR    200                 // floats
#define KR_SMEM_BYTES 232448

__device__ __forceinline__ float gru_cell(float igr, float igz, float ign,
                                          float ar, float az, float an,
                                          float bnv, float hp) {
    const float r = __fdividef(1.f, 1.f + __expf(-(igr + ar)));
    const float z = __fdividef(1.f, 1.f + __expf(-(igz + az)));
    const float a = ign + r * (an + bnv);
    const float n = __fdividef(2.f, 1.f + __expf(-2.f * a)) - 1.f;
    return n + z * (hp - n);
}

__global__ void __launch_bounds__(256, 1) __cluster_dims__(4, 1, 1)
k_rec_mma(const float* __restrict__ Whh, const float* __restrict__ bnb)
{
    extern __shared__ char smr[];
    const uint32_t sb = smem_u32(smr);
    const int tid = threadIdx.x;
    const int wid = tid >> 5, lane = tid & 31;
    const int c   = blockIdx.x & 3;   // cluster rank (unit chunk)
    const int cl  = blockIdx.x >> 2;  // cluster id: batch rows [cl*16, +16)

    // ---- stage W_hh chunk as bf16 hi/lo, local rows [r-units | z | n] ----
    if (tid < 192) {
        const int g = tid >> 6, u = tid & 63;
        const float* src = Whh + ((size_t)(g * 256 + c * 64 + u)) * 256;
        __nv_bfloat16* whi = (__nv_bfloat16*)(smr) + tid * WSTR;
        __nv_bfloat16* wlo = (__nv_bfloat16*)(smr + WLO_B) + tid * WSTR;
#pragma unroll 4
        for (int q = 0; q < 64; q++) {
            __nv_bfloat162 h0, h1, l0, l1;
            split4(*(const float4*)(src + q * 4), h0, h1, l0, l1);
            *(__nv_bfloat162*)(whi + q * 4)     = h0;
            *(__nv_bfloat162*)(whi + q * 4 + 2) = h1;
            *(__nv_bfloat162*)(wlo + q * 4)     = l0;
            *(__nv_bfloat162*)(wlo + q * 4 + 2) = l1;
        }
    }
    // zero h buffers (hi+lo, incl padding)
    for (int i = tid; i < 4224; i += 256) ((uint32_t*)(smr + HHI_B))[i] = 0;
    __syncthreads();
    cluster_sync_();

    // ---- phase-A fragment addresses (warp wid owns n-tiles tn0..tn0+2) ----
    const int tn0 = wid * 3;
    const uint32_t aHi = sb + HHI_B + 2u * ((lane & 15) * WSTR + (lane >> 4) * 8);
    const uint32_t aLo = aHi + (HLO_B - HHI_B);
    uint32_t bAd[3];
#pragma unroll
    for (int nt = 0; nt < 3; nt++)
        bAd[nt] = sb + 2u * (((tn0 + nt) * 8 + (lane & 7)) * WSTR + ((lane >> 3) & 1) * 8);

    // ---- phase-B constants (warp == row-group: rows 2*wid, 2*wid+1) ------
    const int lu  = lane * 2;             // local units lu, lu+1
    const int gu  = c * 64 + lu;
    const int row0 = 2 * wid;
    const float2 bnv = *(const float2*)(bnb + gu);
    const float* ig0 = g_ig + ((size_t)(cl * 16 + row0)) * T_ * G3_ + gu;
    const float* ig1 = ig0 + (size_t)T_ * G3_;
    float* Dm = (float*)(smr + D_B);
    uint32_t pp[4];
#pragma unroll
    for (int r = 0; r < 4; r++) pp[r] = mapa_u32(sb, r);
    const uint32_t offH0 = HHI_B + 2u * (row0 * WSTR + gu);
    const uint32_t offH1 = HHI_B + 2u * ((row0 + 1) * WSTR + gu);
    float2 hp0 = make_float2(0.f, 0.f), hp1 = make_float2(0.f, 0.f);
    const int grp = lane >> 2, qc = (lane & 3) * 2;

    for (int t = 0; t < T_; t++) {
        // prefetch input gates for this thread's 2 rows x 2 units
        const float* p0 = ig0 + (size_t)t * G3_;
        const float* p1 = ig1 + (size_t)t * G3_;
        const float2 gr0 = *(const float2*)(p0);
        const float2 gz0 = *(const float2*)(p0 + 256);
        const float2 gn0 = *(const float2*)(p0 + 512);
        const float2 gr1 = *(const float2*)(p1);
        const float2 gz1 = *(const float2*)(p1 + 256);
        const float2 gn1 = *(const float2*)(p1 + 512);

        // ---- phase A: D = h @ W^T (3 bf16 chains) ----
        float a0[4] = {0.f, 0.f, 0.f, 0.f};
        float a1[4] = {0.f, 0.f, 0.f, 0.f};
        float a2[4] = {0.f, 0.f, 0.f, 0.f};
#pragma unroll
        for (int ks = 0; ks < 16; ks++) {
            const uint32_t ko = (uint32_t)(ks * 32);
            uint32_t ah[4], al[4];
            ldsm_x4(ah, aHi + ko);
            ldsm_x4(al, aLo + ko);
            uint32_t bh0[2], bh1[2], bh2[2], bl0[2], bl1[2], bl2[2];
            ldsm_x2(bh0, bAd[0] + ko);
            ldsm_x2(bh1, bAd[1] + ko);
            ldsm_x2(bh2, bAd[2] + ko);
            ldsm_x2(bl0, bAd[0] + WLO_B + ko);
            ldsm_x2(bl1, bAd[1] + WLO_B + ko);
            ldsm_x2(bl2, bAd[2] + WLO_B + ko);
            mma_bf16(a0, ah, bh0); mma_bf16(a1, ah, bh1); mma_bf16(a2, ah, bh2);
            mma_bf16(a0, ah, bl0); mma_bf16(a1, ah, bl1); mma_bf16(a2, ah, bl2);
            mma_bf16(a0, al, bh0); mma_bf16(a1, al, bh1); mma_bf16(a2, al, bh2);
        }
        // stage D fragments
        {
            const int col = tn0 * 8 + qc;
            *(float2*)(Dm + grp * DSTR + col)            = make_float2(a0[0], a0[1]);
            *(float2*)(Dm + (grp + 8) * DSTR + col)      = make_float2(a0[2], a0[3]);
            *(float2*)(Dm + grp * DSTR + col + 8)        = make_float2(a1[0], a1[1]);
            *(float2*)(Dm + (grp + 8) * DSTR + col + 8)  = make_float2(a1[2], a1[3]);
            *(float2*)(Dm + grp * DSTR + col + 16)       = make_float2(a2[0], a2[1]);
            *(float2*)(Dm + (grp + 8) * DSTR + col + 16) = make_float2(a2[2], a2[3]);
        }
        cluster_sync_();   // D visible; all ranks done reading h

        // ---- phase B: GRU cells + cluster-wide h update ----
        {
            const float2 dr0 = *(const float2*)(Dm + row0 * DSTR + lu);
            const float2 dz0 = *(const float2*)(Dm + row0 * DSTR + 64 + lu);
            const float2 dn0 = *(const float2*)(Dm + row0 * DSTR + 128 + lu);
            const float2 dr1 = *(const float2*)(Dm + (row0 + 1) * DSTR + lu);
            const float2 dz1 = *(const float2*)(Dm + (row0 + 1) * DSTR + 64 + lu);
            const float2 dn1 = *(const float2*)(Dm + (row0 + 1) * DSTR + 128 + lu);

            const float h00 = gru_cell(gr0.x, gz0.x, gn0.x, dr0.x, dz0.x, dn0.x, bnv.x, hp0.x);
            const float h01 = gru_cell(gr0.y, gz0.y, gn0.y, dr0.y, dz0.y, dn0.y, bnv.y, hp0.y);
            const float h10 = gru_cell(gr1.x, gz1.x, gn1.x, dr1.x, dz1.x, dn1.x, bnv.x, hp1.x);
            const float h11 = gru_cell(gr1.y, gz1.y, gn1.y, dr1.y, dz1.y, dn1.y, bnv.y, hp1.y);
            hp0 = make_float2(h00, h01);
            hp1 = make_float2(h10, h11);

            __nv_bfloat162 hi0 = __floats2bfloat162_rn(h00, h01);
            __nv_bfloat162 lo0 = __floats2bfloat162_rn(h00 - __bfloat162float(hi0.x),
                                                       h01 - __bfloat162float(hi0.y));
            __nv_bfloat162 hi1 = __floats2bfloat162_rn(h10, h11);
            __nv_bfloat162 lo1 = __floats2bfloat162_rn(h10 - __bfloat162float(hi1.x),
                                                       h11 - __bfloat162float(hi1.y));
            const uint32_t wh0 = *reinterpret_cast<uint32_t*>(&hi0);
            const uint32_t wl0 = *reinterpret_cast<uint32_t*>(&lo0);
            const uint32_t wh1 = *reinterpret_cast<uint32_t*>(&hi1);
            const uint32_t wl1 = *reinterpret_cast<uint32_t*>(&lo1);
#pragma unroll
            for (int r = 0; r < 4; r++) {
                stc_b32(pp[r] + offH0, wh0);
                stc_b32(pp[r] + offH0 + (HLO_B - HHI_B), wl0);
                stc_b32(pp[r] + offH1, wh1);
                stc_b32(pp[r] + offH1 + (HLO_B - HHI_B), wl1);
            }
        }
        cluster_sync_();   // h_{t+1} visible everywhere
    }

    // final h (in registers) -> g_hfin
    *(float2*)(g_hfin + (size_t)(cl * 16 + row0) * H_ + gu)     = hp0;
    *(float2*)(g_hfin + (size_t)(cl * 16 + row0 + 1) * H_ + gu) = hp1;
}

// ---------------------------------------------------------------------------
// Phase 3: out = h_final @ w_lin^T + bias_out   (512 x 128, trivial)
// ---------------------------------------------------------------------------
__global__ void __launch_bounds__(128) k_out(const float* __restrict__ wl,
                                             const float* __restrict__ bo,
                                             float* __restrict__ out)
{
    __shared__ float sh[256];
    const int b = blockIdx.x, o = threadIdx.x;
    sh[o]       = g_hfin[(size_t)b * H_ + o];
    sh[o + 128] = g_hfin[(size_t)b * H_ + o + 128];
    __syncthreads();

    float acc = bo[o];
    const float4* wp = (const float4*)(wl + (size_t)o * H_);
#pragma unroll 8
    for (int q = 0; q < 64; q++) {
        const float4 w = wp[q];
        const float4 h = *(const float4*)(sh + q * 4);
        acc += w.x * h.x + w.y * h.y + w.z * h.z + w.w * h.w;
    }
    out[(size_t)b * OUT_ + o] = acc;
}

// ---------------------------------------------------------------------------
extern "C" void kernel_launch(void* const* d_in, const int* in_sizes, int n_in,
                              void* d_out, int out_size)
{
    (void)in_sizes; (void)n_in; (void)out_size;
    const float* x   = (const float*)d_in[0];  // (B,T,IN)
    const float* wih = (const float*)d_in[1];  // (3H,IN)
    const float* whh = (const float*)d_in[2];  // (3H,H)
    const float* bg  = (const float*)d_in[3];  // (3H)
    const float* bnn = (const float*)d_in[4];  // (H)
    const float* wl  = (const float*)d_in[5];  // (OUT,H)
    const float* bo  = (const float*)d_in[6];  // (OUT)
    float* out = (float*)d_out;                // (B,OUT)

    cudaFuncSetAttribute(k_ih_mma,  cudaFuncAttributeMaxDynamicSharedMemorySize, P1_SMEM_BYTES);
    cudaFuncSetAttribute(k_rec_mma, cudaFuncAttributeMaxDynamicSharedMemorySize, KR_SMEM_BYTES);

    k_ih_mma<<<dim3(G3_ / 128, (B_ * T_) / 128), 256, P1_SMEM_BYTES>>>(x, wih, bg);
    k_rec_mma<<<128, 256, KR_SMEM_BYTES>>>(whh, bnn);
    k_out<<<B_, 128>>>(wl, bo, out);
}

// round 14
// speedup vs baseline: 1.2624x; 1.1168x over previous
#include <cuda_runtime.h>
#include <cuda_bf16.h>
#include <cstdint>
#include <math.h>

// Problem dims
#define B_   512
#define T_   512
#define IN_  128
#define H_   256
#define G3_  768   // 3*H
#define OUT_ 128

__device__ float g_ig[(size_t)B_ * T_ * G3_];     // ~805 MB  [B][T][3H]
__device__ float g_hfin[(size_t)B_ * H_];

typedef unsigned long long ull;

// ---------------- generic smem / cluster helpers ---------------------------
__device__ __forceinline__ uint32_t smem_u32(const void* p) {
    uint32_t a;
    asm("{ .reg .u64 t; cvta.to.shared.u64 t, %1; cvt.u32.u64 %0, t; }" : "=r"(a) : "l"(p));
    return a;
}
__device__ __forceinline__ uint32_t mapa_u32(uint32_t a, uint32_t rank) {
    uint32_t r;
    asm("mapa.shared::cluster.u32 %0, %1, %2;" : "=r"(r) : "r"(a), "r"(rank));
    return r;
}
__device__ __forceinline__ void stc_b32(uint32_t a, uint32_t v) {
    asm volatile("st.shared::cluster.u32 [%0], %1;" :: "r"(a), "r"(v) : "memory");
}
__device__ __forceinline__ void cluster_sync_() {
    asm volatile("barrier.cluster.arrive.aligned;" ::: "memory");
    asm volatile("barrier.cluster.wait.aligned;"   ::: "memory");
}

// ---------------- mma.sync helpers (sm_80-era HMMA, valid on sm_100) -------
__device__ __forceinline__ void ldsm_x4(uint32_t* r, uint32_t addr) {
    asm volatile("ldmatrix.sync.aligned.m8n8.x4.shared.b16 {%0,%1,%2,%3}, [%4];"
                 : "=r"(r[0]), "=r"(r[1]), "=r"(r[2]), "=r"(r[3]) : "r"(addr));
}
__device__ __forceinline__ void ldsm_x2(uint32_t* r, uint32_t addr) {
    asm volatile("ldmatrix.sync.aligned.m8n8.x2.shared.b16 {%0,%1}, [%2];"
                 : "=r"(r[0]), "=r"(r[1]) : "r"(addr));
}
__device__ __forceinline__ void mma_bf16(float* d, const uint32_t* a, const uint32_t* b) {
    asm volatile(
        "mma.sync.aligned.m16n8k16.row.col.f32.bf16.bf16.f32 "
        "{%0,%1,%2,%3}, {%4,%5,%6,%7}, {%8,%9}, {%0,%1,%2,%3};"
        : "+f"(d[0]), "+f"(d[1]), "+f"(d[2]), "+f"(d[3])
        : "r"(a[0]), "r"(a[1]), "r"(a[2]), "r"(a[3]), "r"(b[0]), "r"(b[1]));
}

// bf16 hi/lo split of a float4 -> 4 packed bf16x2 (hi pair0, hi pair1, lo0, lo1)
__device__ __forceinline__ void split4(const float4 v,
                                       __nv_bfloat162& h0, __nv_bfloat162& h1,
                                       __nv_bfloat162& l0, __nv_bfloat162& l1) {
    h0 = __floats2bfloat162_rn(v.x, v.y);
    h1 = __floats2bfloat162_rn(v.z, v.w);
    l0 = __floats2bfloat162_rn(v.x - __bfloat162float(h0.x), v.y - __bfloat162float(h0.y));
    l1 = __floats2bfloat162_rn(v.z - __bfloat162float(h1.x), v.w - __bfloat162float(h1.y));
}

// ---------------------------------------------------------------------------
// Phase 1 (HMMA): ig = X @ W_ih^T + bias via bf16-split mma.sync.
// 128x128 CTA tile, 8 warps = 4m x 2n, each warp 32x64 (proven 818 us).
// ---------------------------------------------------------------------------
#define P1_STR  72
#define AHI_OFF 0
#define ALO_OFF (128 * P1_STR * 2)
#define BHI_OFF (2 * 128 * P1_STR * 2)
#define BLO_OFF (BHI_OFF + 128 * P1_STR * 2)
#define P1_SMEM_BYTES (BLO_OFF + 128 * P1_STR * 2)  // 73728

__global__ void __launch_bounds__(256, 2)
k_ih_mma(const float* __restrict__ X, const float* __restrict__ W,
         const float* __restrict__ bias)
{
    extern __shared__ char smc[];
    const uint32_t sb = smem_u32(smc);
    const int tid  = threadIdx.x;
    const int wid  = tid >> 5, lane = tid & 31;
    const int bn   = blockIdx.x;
    const int bm   = blockIdx.y;

    const int wm = wid & 3;
    const int wn = wid >> 2;

    const uint32_t aHi0 = sb + AHI_OFF + 2u * ((wm * 32 + (lane & 15)) * P1_STR + (lane >> 4) * 8);
    const uint32_t aLo0 = aHi0 + ALO_OFF;
    const uint32_t bHi0 = sb + BHI_OFF + 2u * ((wn * 64 + ((lane >> 4) & 1) * 8 + (lane & 7)) * P1_STR
                                               + ((lane >> 3) & 1) * 8);
    const uint32_t bLo0 = bHi0 + (BLO_OFF - BHI_OFF);

    float acc[2][8][4];
#pragma unroll
    for (int mt = 0; mt < 2; mt++)
#pragma unroll
        for (int nt = 0; nt < 8; nt++)
#pragma unroll
            for (int e = 0; e < 4; e++) acc[mt][nt][e] = 0.f;

    for (int kk = 0; kk < 128; kk += 64) {
        if (kk) __syncthreads();
        {
            const int row = tid >> 1;
            const int kp  = (tid & 1) * 32;
            const float* xs = X + ((size_t)(bm * 128 + row)) * 128 + kk + kp;
            const float* ws = W + ((size_t)(bn * 128 + row)) * 128 + kk + kp;
            __nv_bfloat16* ah = (__nv_bfloat16*)(smc + AHI_OFF) + row * P1_STR + kp;
            __nv_bfloat16* al = (__nv_bfloat16*)(smc + ALO_OFF) + row * P1_STR + kp;
            __nv_bfloat16* bh = (__nv_bfloat16*)(smc + BHI_OFF) + row * P1_STR + kp;
            __nv_bfloat16* bl = (__nv_bfloat16*)(smc + BLO_OFF) + row * P1_STR + kp;
#pragma unroll
            for (int q = 0; q < 8; q++) {
                __nv_bfloat162 h0, h1, l0, l1;
                split4(*(const float4*)(xs + q * 4), h0, h1, l0, l1);
                *(__nv_bfloat162*)(ah + q * 4)     = h0;
                *(__nv_bfloat162*)(ah + q * 4 + 2) = h1;
                *(__nv_bfloat162*)(al + q * 4)     = l0;
                *(__nv_bfloat162*)(al + q * 4 + 2) = l1;
                split4(*(const float4*)(ws + q * 4), h0, h1, l0, l1);
                *(__nv_bfloat162*)(bh + q * 4)     = h0;
                *(__nv_bfloat162*)(bh + q * 4 + 2) = h1;
                *(__nv_bfloat162*)(bl + q * 4)     = l0;
                *(__nv_bfloat162*)(bl + q * 4 + 2) = l1;
            }
        }
        __syncthreads();

#pragma unroll
        for (int ks = 0; ks < 4; ks++) {
            const uint32_t ko = (uint32_t)(ks * 32);
            uint32_t ah[2][4], bh[4][4];
#pragma unroll
            for (int mt = 0; mt < 2; mt++)
                ldsm_x4(ah[mt], aHi0 + (uint32_t)(mt * 16 * P1_STR * 2) + ko);
#pragma unroll
            for (int np = 0; np < 4; np++)
                ldsm_x4(bh[np], bHi0 + (uint32_t)(np * 16 * P1_STR * 2) + ko);
#pragma unroll
            for (int mt = 0; mt < 2; mt++)
#pragma unroll
                for (int nt = 0; nt < 8; nt++)
                    mma_bf16(acc[mt][nt], ah[mt], &bh[nt >> 1][(nt & 1) * 2]);
            {
                uint32_t bl[4][4];
#pragma unroll
                for (int np = 0; np < 4; np++)
                    ldsm_x4(bl[np], bLo0 + (uint32_t)(np * 16 * P1_STR * 2) + ko);
#pragma unroll
                for (int mt = 0; mt < 2; mt++)
#pragma unroll
                    for (int nt = 0; nt < 8; nt++)
                        mma_bf16(acc[mt][nt], ah[mt], &bl[nt >> 1][(nt & 1) * 2]);
            }
            {
                uint32_t al[2][4];
#pragma unroll
                for (int mt = 0; mt < 2; mt++)
                    ldsm_x4(al[mt], aLo0 + (uint32_t)(mt * 16 * P1_STR * 2) + ko);
#pragma unroll
                for (int mt = 0; mt < 2; mt++)
#pragma unroll
                    for (int nt = 0; nt < 8; nt++)
                        mma_bf16(acc[mt][nt], al[mt], &bh[nt >> 1][(nt & 1) * 2]);
            }
        }
    }

    const int grp = lane >> 2;
    const int qc  = (lane & 3) * 2;
#pragma unroll
    for (int mt = 0; mt < 2; mt++) {
        const int r0 = bm * 128 + wm * 32 + mt * 16 + grp;
#pragma unroll
        for (int nt = 0; nt < 8; nt++) {
            const int col = bn * 128 + wn * 64 + nt * 8 + qc;
            const float2 bb = *(const float2*)(bias + col);
            float* d0 = g_ig + (size_t)r0 * G3_ + col;
            float* d1 = d0 + (size_t)8 * G3_;
            *(float2*)d0 = make_float2(acc[mt][nt][0] + bb.x, acc[mt][nt][1] + bb.y);
            *(float2*)d1 = make_float2(acc[mt][nt][2] + bb.x, acc[mt][nt][3] + bb.y);
        }
    }
}

// ---------------------------------------------------------------------------
// Phase 2 (HMMA): GRU recurrence, v2.
//   - W-hi fragments preloaded into REGISTERS (96/thread) at init; only
//     h(hi/lo) + W-lo come from smem per step (14 wf/warp/ks vs 20).
//   - h double-buffered (read buf[p], write buf[1-p]) -> ONE cluster sync
//     per step (plus a cheap __syncthreads for the CTA-local D slab).
// smem: [0,101376) W-lo | [101376,202752) W-hi staging at init, then
//       hHi0/hLo0/hHi1/hLo1 (4 x 8448) + D (12800).
// ---------------------------------------------------------------------------
#define WSTR    264                 // bf16/row (256+8)
#define WLO_B   0
#define STG_B   101376
#define HH0_B   101376
#define HL0_B   109824
#define HH1_B   118272
#define HL1_B   126720
#define D_B     135168
#define DSTR    200                 // floats
#define KR_SMEM_BYTES 202752

__device__ __forceinline__ float gru_cell(float igr, float igz, float ign,
                                          float ar, float az, float an,
                                          float bnv, float hp) {
    const float r = __fdividef(1.f, 1.f + __expf(-(igr + ar)));
    const float z = __fdividef(1.f, 1.f + __expf(-(igz + az)));
    const float a = ign + r * (an + bnv);
    const float n = __fdividef(2.f, 1.f + __expf(-2.f * a)) - 1.f;
    return n + z * (hp - n);
}

__global__ void __launch_bounds__(256, 1) __cluster_dims__(4, 1, 1)
k_rec_mma(const float* __restrict__ Whh, const float* __restrict__ bnb)
{
    extern __shared__ char smr[];
    const uint32_t sb = smem_u32(smr);
    const int tid = threadIdx.x;
    const int wid = tid >> 5, lane = tid & 31;
    const int c   = blockIdx.x & 3;   // cluster rank (unit chunk)
    const int cl  = blockIdx.x >> 2;  // cluster id: batch rows [cl*16, +16)

    // ---- stage W_hh chunk: hi -> staging region, lo -> persistent region --
    if (tid < 192) {
        const int g = tid >> 6, u = tid & 63;
        const float* src = Whh + ((size_t)(g * 256 + c * 64 + u)) * 256;
        __nv_bfloat16* whi = (__nv_bfloat16*)(smr + STG_B) + tid * WSTR;
        __nv_bfloat16* wlo = (__nv_bfloat16*)(smr + WLO_B) + tid * WSTR;
#pragma unroll 4
        for (int q = 0; q < 64; q++) {
            __nv_bfloat162 h0, h1, l0, l1;
            split4(*(const float4*)(src + q * 4), h0, h1, l0, l1);
            *(__nv_bfloat162*)(whi + q * 4)     = h0;
            *(__nv_bfloat162*)(whi + q * 4 + 2) = h1;
            *(__nv_bfloat162*)(wlo + q * 4)     = l0;
            *(__nv_bfloat162*)(wlo + q * 4 + 2) = l1;
        }
    }
    __syncthreads();

    // ---- preload W-hi fragments into registers (warp wid: n-tiles tn0..+2) -
    const int tn0 = wid * 3;
    uint32_t bhi[3][16][2];
    {
#pragma unroll
        for (int nt = 0; nt < 3; nt++) {
            const uint32_t base = sb + STG_B
                + 2u * (((tn0 + nt) * 8 + (lane & 7)) * WSTR + ((lane >> 3) & 1) * 8);
#pragma unroll
            for (int ks = 0; ks < 16; ks++)
                ldsm_x2(bhi[nt][ks], base + (uint32_t)(ks * 32));
        }
    }
    __syncthreads();   // all fragment reads done before staging is reused

    // zero both h buffers (hi+lo x2 = 33792 B = 8448 words)
    for (int i = tid; i < 8448; i += 256) ((uint32_t*)(smr + HH0_B))[i] = 0;
    __syncthreads();
    cluster_sync_();   // peers' h buffers zeroed before any remote store

    // ---- per-buffer phase-A h fragment addresses -------------------------
    const uint32_t hfo = 2u * ((lane & 15) * WSTR + (lane >> 4) * 8);
    const uint32_t aHiP[2] = { sb + HH0_B + hfo, sb + HH1_B + hfo };
    // W-lo fragment addresses (persistent region)
    uint32_t blAd[3];
#pragma unroll
    for (int nt = 0; nt < 3; nt++)
        blAd[nt] = sb + WLO_B + 2u * (((tn0 + nt) * 8 + (lane & 7)) * WSTR + ((lane >> 3) & 1) * 8);

    // ---- phase-B constants (warp == row-group: rows 2*wid, 2*wid+1) ------
    const int lu  = lane * 2;
    const int gu  = c * 64 + lu;
    const int row0 = 2 * wid;
    const float2 bnv = *(const float2*)(bnb + gu);
    const float* ig0 = g_ig + ((size_t)(cl * 16 + row0)) * T_ * G3_ + gu;
    const float* ig1 = ig0 + (size_t)T_ * G3_;
    float* Dm = (float*)(smr + D_B);
    uint32_t pp[4];
#pragma unroll
    for (int r = 0; r < 4; r++) pp[r] = mapa_u32(sb, r);
    const uint32_t ho0 = 2u * (row0 * WSTR + gu);         // + buffer base
    const uint32_t ho1 = 2u * ((row0 + 1) * WSTR + gu);
    const uint32_t hbase[2] = { HH0_B, HH1_B };           // lo = +8448
    float2 hp0 = make_float2(0.f, 0.f), hp1 = make_float2(0.f, 0.f);
    const int grp = lane >> 2, qc = (lane & 3) * 2;

    for (int t = 0; t < T_; t++) {
        const int p  = t & 1;        // read buffer
        const int pw = p ^ 1;        // write buffer

        // prefetch input gates for this thread's 2 rows x 2 units
        const float* q0 = ig0 + (size_t)t * G3_;
        const float* q1 = ig1 + (size_t)t * G3_;
        const float2 gr0 = *(const float2*)(q0);
        const float2 gz0 = *(const float2*)(q0 + 256);
        const float2 gn0 = *(const float2*)(q0 + 512);
        const float2 gr1 = *(const float2*)(q1);
        const float2 gz1 = *(const float2*)(q1 + 256);
        const float2 gn1 = *(const float2*)(q1 + 512);

        // ---- phase A: D = h @ W^T (3 bf16 chains; W-hi from registers) ----
        float a0[4] = {0.f, 0.f, 0.f, 0.f};
        float a1[4] = {0.f, 0.f, 0.f, 0.f};
        float a2[4] = {0.f, 0.f, 0.f, 0.f};
        const uint32_t aHi = aHiP[p];
        const uint32_t aLo = aHi + 8448u;
#pragma unroll
        for (int ks = 0; ks < 16; ks++) {
            const uint32_t ko = (uint32_t)(ks * 32);
            uint32_t ah[4], al[4];
            ldsm_x4(ah, aHi + ko);
            ldsm_x4(al, aLo + ko);
            uint32_t bl0[2], bl1[2], bl2[2];
            ldsm_x2(bl0, blAd[0] + ko);
            ldsm_x2(bl1, blAd[1] + ko);
            ldsm_x2(bl2, blAd[2] + ko);
            mma_bf16(a0, ah, bhi[0][ks]); mma_bf16(a1, ah, bhi[1][ks]); mma_bf16(a2, ah, bhi[2][ks]);
            mma_bf16(a0, ah, bl0);        mma_bf16(a1, ah, bl1);        mma_bf16(a2, ah, bl2);
            mma_bf16(a0, al, bhi[0][ks]); mma_bf16(a1, al, bhi[1][ks]); mma_bf16(a2, al, bhi[2][ks]);
        }
        // stage D fragments (CTA-local slab)
        {
            const int col = tn0 * 8 + qc;
            *(float2*)(Dm + grp * DSTR + col)            = make_float2(a0[0], a0[1]);
            *(float2*)(Dm + (grp + 8) * DSTR + col)      = make_float2(a0[2], a0[3]);
            *(float2*)(Dm + grp * DSTR + col + 8)        = make_float2(a1[0], a1[1]);
            *(float2*)(Dm + (grp + 8) * DSTR + col + 8)  = make_float2(a1[2], a1[3]);
            *(float2*)(Dm + grp * DSTR + col + 16)       = make_float2(a2[0], a2[1]);
            *(float2*)(Dm + (grp + 8) * DSTR + col + 16) = make_float2(a2[2], a2[3]);
        }
        __syncthreads();   // D visible CTA-locally

        // ---- phase B: GRU cells + cluster-wide h update (to buf pw) ------
        {
            const float2 dr0 = *(const float2*)(Dm + row0 * DSTR + lu);
            const float2 dz0 = *(const float2*)(Dm + row0 * DSTR + 64 + lu);
            const float2 dn0 = *(const float2*)(Dm + row0 * DSTR + 128 + lu);
            const float2 dr1 = *(const float2*)(Dm + (row0 + 1) * DSTR + lu);
            const float2 dz1 = *(const float2*)(Dm + (row0 + 1) * DSTR + 64 + lu);
            const float2 dn1 = *(const float2*)(Dm + (row0 + 1) * DSTR + 128 + lu);

            const float h00 = gru_cell(gr0.x, gz0.x, gn0.x, dr0.x, dz0.x, dn0.x, bnv.x, hp0.x);
            const float h01 = gru_cell(gr0.y, gz0.y, gn0.y, dr0.y, dz0.y, dn0.y, bnv.y, hp0.y);
            const float h10 = gru_cell(gr1.x, gz1.x, gn1.x, dr1.x, dz1.x, dn1.x, bnv.x, hp1.x);
            const float h11 = gru_cell(gr1.y, gz1.y, gn1.y, dr1.y, dz1.y, dn1.y, bnv.y, hp1.y);
            hp0 = make_float2(h00, h01);
            hp1 = make_float2(h10, h11);

            __nv_bfloat162 hi0 = __floats2bfloat162_rn(h00, h01);
            __nv_bfloat162 lo0 = __floats2bfloat162_rn(h00 - __bfloat162float(hi0.x),
                                                       h01 - __bfloat162float(hi0.y));
            __nv_bfloat162 hi1 = __floats2bfloat162_rn(h10, h11);
            __nv_bfloat162 lo1 = __floats2bfloat162_rn(h10 - __bfloat162float(hi1.x),
                                                       h11 - __bfloat162float(hi1.y));
            const uint32_t wh0 = *reinterpret_cast<uint32_t*>(&hi0);
            const uint32_t wl0 = *reinterpret_cast<uint32_t*>(&lo0);
            const uint32_t wh1 = *reinterpret_cast<uint32_t*>(&hi1);
            const uint32_t wl1 = *reinterpret_cast<uint32_t*>(&lo1);
            const uint32_t hb = hbase[pw];
#pragma unroll
            for (int r = 0; r < 4; r++) {
                stc_b32(pp[r] + hb + ho0,         wh0);
                stc_b32(pp[r] + hb + ho0 + 8448u, wl0);
                stc_b32(pp[r] + hb + ho1,         wh1);
                stc_b32(pp[r] + hb + ho1 + 8448u, wl1);
            }
        }
        cluster_sync_();   // h_{t+1} visible everywhere; step boundary
    }

    // final h (in registers) -> g_hfin
    *(float2*)(g_hfin + (size_t)(cl * 16 + row0) * H_ + gu)     = hp0;
    *(float2*)(g_hfin + (size_t)(cl * 16 + row0 + 1) * H_ + gu) = hp1;
}

// ---------------------------------------------------------------------------
// Phase 3: out = h_final @ w_lin^T + bias_out   (512 x 128, trivial)
// ---------------------------------------------------------------------------
__global__ void __launch_bounds__(128) k_out(const float* __restrict__ wl,
                                             const float* __restrict__ bo,
                                             float* __restrict__ out)
{
    __shared__ float sh[256];
    const int b = blockIdx.x, o = threadIdx.x;
    sh[o]       = g_hfin[(size_t)b * H_ + o];
    sh[o + 128] = g_hfin[(size_t)b * H_ + o + 128];
    __syncthreads();

    float acc = bo[o];
    const float4* wp = (const float4*)(wl + (size_t)o * H_);
#pragma unroll 8
    for (int q = 0; q < 64; q++) {
        const float4 w = wp[q];
        const float4 h = *(const float4*)(sh + q * 4);
        acc += w.x * h.x + w.y * h.y + w.z * h.z + w.w * h.w;
    }
    out[(size_t)b * OUT_ + o] = acc;
}

// ---------------------------------------------------------------------------
extern "C" void kernel_launch(void* const* d_in, const int* in_sizes, int n_in,
                              void* d_out, int out_size)
{
    (void)in_sizes; (void)n_in; (void)out_size;
    const float* x   = (const float*)d_in[0];  // (B,T,IN)
    const float* wih = (const float*)d_in[1];  // (3H,IN)
    const float* whh = (const float*)d_in[2];  // (3H,H)
    const float* bg  = (const float*)d_in[3];  // (3H)
    const float* bnn = (const float*)d_in[4];  // (H)
    const float* wl  = (const float*)d_in[5];  // (OUT,H)
    const float* bo  = (const float*)d_in[6];  // (OUT)
    float* out = (float*)d_out;                // (B,OUT)

    cudaFuncSetAttribute(k_ih_mma,  cudaFuncAttributeMaxDynamicSharedMemorySize, P1_SMEM_BYTES);
    cudaFuncSetAttribute(k_rec_mma, cudaFuncAttributeMaxDynamicSharedMemorySize, KR_SMEM_BYTES);

    k_ih_mma<<<dim3(G3_ / 128, (B_ * T_) / 128), 256, P1_SMEM_BYTES>>>(x, wih, bg);
    k_rec_mma<<<128, 256, KR_SMEM_BYTES>>>(whh, bnn);
    k_out<<<B_, 128>>>(wl, bo, out);
}

// round 15
// speedup vs baseline: 1.2663x; 1.0031x over previous
#include <cuda_runtime.h>
#include <cuda_bf16.h>
#include <cstdint>
#include <math.h>

// Problem dims
#define B_   512
#define T_   512
#define IN_  128
#define H_   256
#define G3_  768   // 3*H
#define OUT_ 128

__device__ float g_ig[(size_t)B_ * T_ * G3_];     // ~805 MB  [B][T][3H]
__device__ float g_hfin[(size_t)B_ * H_];

typedef unsigned long long ull;

// ---------------- generic smem / cluster helpers ---------------------------
__device__ __forceinline__ uint32_t smem_u32(const void* p) {
    uint32_t a;
    asm("{ .reg .u64 t; cvta.to.shared.u64 t, %1; cvt.u32.u64 %0, t; }" : "=r"(a) : "l"(p));
    return a;
}
__device__ __forceinline__ uint32_t mapa_u32(uint32_t a, uint32_t rank) {
    uint32_t r;
    asm("mapa.shared::cluster.u32 %0, %1, %2;" : "=r"(r) : "r"(a), "r"(rank));
    return r;
}
__device__ __forceinline__ void stc_b32(uint32_t a, uint32_t v) {
    asm volatile("st.shared::cluster.u32 [%0], %1;" :: "r"(a), "r"(v) : "memory");
}
__device__ __forceinline__ void cluster_sync_() {
    asm volatile("barrier.cluster.arrive.aligned;" ::: "memory");
    asm volatile("barrier.cluster.wait.aligned;"   ::: "memory");
}

// ---------------- mma.sync helpers (sm_80-era HMMA, valid on sm_100) -------
__device__ __forceinline__ void ldsm_x4(uint32_t* r, uint32_t addr) {
    asm volatile("ldmatrix.sync.aligned.m8n8.x4.shared.b16 {%0,%1,%2,%3}, [%4];"
                 : "=r"(r[0]), "=r"(r[1]), "=r"(r[2]), "=r"(r[3]) : "r"(addr));
}
__device__ __forceinline__ void ldsm_x2(uint32_t* r, uint32_t addr) {
    asm volatile("ldmatrix.sync.aligned.m8n8.x2.shared.b16 {%0,%1}, [%2];"
                 : "=r"(r[0]), "=r"(r[1]) : "r"(addr));
}
__device__ __forceinline__ void mma_bf16(float* d, const uint32_t* a, const uint32_t* b) {
    asm volatile(
        "mma.sync.aligned.m16n8k16.row.col.f32.bf16.bf16.f32 "
        "{%0,%1,%2,%3}, {%4,%5,%6,%7}, {%8,%9}, {%0,%1,%2,%3};"
        : "+f"(d[0]), "+f"(d[1]), "+f"(d[2]), "+f"(d[3])
        : "r"(a[0]), "r"(a[1]), "r"(a[2]), "r"(a[3]), "r"(b[0]), "r"(b[1]));
}

// bf16 hi/lo split of a float4 -> 4 packed bf16x2 (hi pair0, hi pair1, lo0, lo1)
__device__ __forceinline__ void split4(const float4 v,
                                       __nv_bfloat162& h0, __nv_bfloat162& h1,
                                       __nv_bfloat162& l0, __nv_bfloat162& l1) {
    h0 = __floats2bfloat162_rn(v.x, v.y);
    h1 = __floats2bfloat162_rn(v.z, v.w);
    l0 = __floats2bfloat162_rn(v.x - __bfloat162float(h0.x), v.y - __bfloat162float(h0.y));
    l1 = __floats2bfloat162_rn(v.z - __bfloat162float(h1.x), v.w - __bfloat162float(h1.y));
}

// ---------------------------------------------------------------------------
// Phase 1 (HMMA): ig = X @ W_ih^T + bias via bf16-split mma.sync.
// 128x128 CTA tile, 8 warps = 4m x 2n, each warp 32x64 (proven 814 us).
// ---------------------------------------------------------------------------
#define P1_STR  72
#define AHI_OFF 0
#define ALO_OFF (128 * P1_STR * 2)
#define BHI_OFF (2 * 128 * P1_STR * 2)
#define BLO_OFF (BHI_OFF + 128 * P1_STR * 2)
#define P1_SMEM_BYTES (BLO_OFF + 128 * P1_STR * 2)  // 73728

__global__ void __launch_bounds__(256, 2)
k_ih_mma(const float* __restrict__ X, const float* __restrict__ W,
         const float* __restrict__ bias)
{
    extern __shared__ char smc[];
    const uint32_t sb = smem_u32(smc);
    const int tid  = threadIdx.x;
    const int wid  = tid >> 5, lane = tid & 31;
    const int bn   = blockIdx.x;
    const int bm   = blockIdx.y;

    const int wm = wid & 3;
    const int wn = wid >> 2;

    const uint32_t aHi0 = sb + AHI_OFF + 2u * ((wm * 32 + (lane & 15)) * P1_STR + (lane >> 4) * 8);
    const uint32_t aLo0 = aHi0 + ALO_OFF;
    const uint32_t bHi0 = sb + BHI_OFF + 2u * ((wn * 64 + ((lane >> 4) & 1) * 8 + (lane & 7)) * P1_STR
                                               + ((lane >> 3) & 1) * 8);
    const uint32_t bLo0 = bHi0 + (BLO_OFF - BHI_OFF);

    float acc[2][8][4];
#pragma unroll
    for (int mt = 0; mt < 2; mt++)
#pragma unroll
        for (int nt = 0; nt < 8; nt++)
#pragma unroll
            for (int e = 0; e < 4; e++) acc[mt][nt][e] = 0.f;

    for (int kk = 0; kk < 128; kk += 64) {
        if (kk) __syncthreads();
        {
            const int row = tid >> 1;
            const int kp  = (tid & 1) * 32;
            const float* xs = X + ((size_t)(bm * 128 + row)) * 128 + kk + kp;
            const float* ws = W + ((size_t)(bn * 128 + row)) * 128 + kk + kp;
            __nv_bfloat16* ah = (__nv_bfloat16*)(smc + AHI_OFF) + row * P1_STR + kp;
            __nv_bfloat16* al = (__nv_bfloat16*)(smc + ALO_OFF) + row * P1_STR + kp;
            __nv_bfloat16* bh = (__nv_bfloat16*)(smc + BHI_OFF) + row * P1_STR + kp;
            __nv_bfloat16* bl = (__nv_bfloat16*)(smc + BLO_OFF) + row * P1_STR + kp;
#pragma unroll
            for (int q = 0; q < 8; q++) {
                __nv_bfloat162 h0, h1, l0, l1;
                split4(*(const float4*)(xs + q * 4), h0, h1, l0, l1);
                *(__nv_bfloat162*)(ah + q * 4)     = h0;
                *(__nv_bfloat162*)(ah + q * 4 + 2) = h1;
                *(__nv_bfloat162*)(al + q * 4)     = l0;
                *(__nv_bfloat162*)(al + q * 4 + 2) = l1;
                split4(*(const float4*)(ws + q * 4), h0, h1, l0, l1);
                *(__nv_bfloat162*)(bh + q * 4)     = h0;
                *(__nv_bfloat162*)(bh + q * 4 + 2) = h1;
                *(__nv_bfloat162*)(bl + q * 4)     = l0;
                *(__nv_bfloat162*)(bl + q * 4 + 2) = l1;
            }
        }
        __syncthreads();

#pragma unroll
        for (int ks = 0; ks < 4; ks++) {
            const uint32_t ko = (uint32_t)(ks * 32);
            uint32_t ah[2][4], bh[4][4];
#pragma unroll
            for (int mt = 0; mt < 2; mt++)
                ldsm_x4(ah[mt], aHi0 + (uint32_t)(mt * 16 * P1_STR * 2) + ko);
#pragma unroll
            for (int np = 0; np < 4; np++)
                ldsm_x4(bh[np], bHi0 + (uint32_t)(np * 16 * P1_STR * 2) + ko);
#pragma unroll
            for (int mt = 0; mt < 2; mt++)
#pragma unroll
                for (int nt = 0; nt < 8; nt++)
                    mma_bf16(acc[mt][nt], ah[mt], &bh[nt >> 1][(nt & 1) * 2]);
            {
                uint32_t bl[4][4];
#pragma unroll
                for (int np = 0; np < 4; np++)
                    ldsm_x4(bl[np], bLo0 + (uint32_t)(np * 16 * P1_STR * 2) + ko);
#pragma unroll
                for (int mt = 0; mt < 2; mt++)
#pragma unroll
                    for (int nt = 0; nt < 8; nt++)
                        mma_bf16(acc[mt][nt], ah[mt], &bl[nt >> 1][(nt & 1) * 2]);
            }
            {
                uint32_t al[2][4];
#pragma unroll
                for (int mt = 0; mt < 2; mt++)
                    ldsm_x4(al[mt], aLo0 + (uint32_t)(mt * 16 * P1_STR * 2) + ko);
#pragma unroll
                for (int mt = 0; mt < 2; mt++)
#pragma unroll
                    for (int nt = 0; nt < 8; nt++)
                        mma_bf16(acc[mt][nt], al[mt], &bh[nt >> 1][(nt & 1) * 2]);
            }
        }
    }

    const int grp = lane >> 2;
    const int qc  = (lane & 3) * 2;
#pragma unroll
    for (int mt = 0; mt < 2; mt++) {
        const int r0 = bm * 128 + wm * 32 + mt * 16 + grp;
#pragma unroll
        for (int nt = 0; nt < 8; nt++) {
            const int col = bn * 128 + wn * 64 + nt * 8 + qc;
            const float2 bb = *(const float2*)(bias + col);
            float* d0 = g_ig + (size_t)r0 * G3_ + col;
            float* d1 = d0 + (size_t)8 * G3_;
            *(float2*)d0 = make_float2(acc[mt][nt][0] + bb.x, acc[mt][nt][1] + bb.y);
            *(float2*)d1 = make_float2(acc[mt][nt][2] + bb.x, acc[mt][nt][3] + bb.y);
        }
    }
}

// ---------------------------------------------------------------------------
// Phase 2 (HMMA): GRU recurrence, v3: 12 warps (384 thr, 3/SMSP) for latency
// hiding; each warp owns 2 n-tiles (W-hi in 64 regs). Phase B on warps 0-7.
// h double-buffered, one cluster sync per step.
// smem: [0,101376) W-lo | [101376,202752) W-hi staging at init, then
//       hHi0/hLo0/hHi1/hLo1 (4 x 8448) + D (12800).
// ---------------------------------------------------------------------------
#define WSTR    264                 // bf16/row (256+8)
#define WLO_B   0
#define STG_B   101376
#define HH0_B   101376
#define HH1_B   118272
#define D_B     135168
#define DSTR    200                 // floats
#define KR_SMEM_BYTES 202752
#define KR_THREADS 384

__device__ __forceinline__ float gru_cell(float igr, float igz, float ign,
                                          float ar, float az, float an,
                                          float bnv, float hp) {
    const float r = __fdividef(1.f, 1.f + __expf(-(igr + ar)));
    const float z = __fdividef(1.f, 1.f + __expf(-(igz + az)));
    const float a = ign + r * (an + bnv);
    const float n = __fdividef(2.f, 1.f + __expf(-2.f * a)) - 1.f;
    return n + z * (hp - n);
}

__global__ void __launch_bounds__(KR_THREADS, 1) __cluster_dims__(4, 1, 1)
k_rec_mma(const float* __restrict__ Whh, const float* __restrict__ bnb)
{
    extern __shared__ char smr[];
    const uint32_t sb = smem_u32(smr);
    const int tid = threadIdx.x;
    const int wid = tid >> 5, lane = tid & 31;
    const int c   = blockIdx.x & 3;   // cluster rank (unit chunk)
    const int cl  = blockIdx.x >> 2;  // cluster id: batch rows [cl*16, +16)

    // ---- stage W_hh chunk: hi -> staging region, lo -> persistent region --
    if (tid < 192) {
        const int g = tid >> 6, u = tid & 63;
        const float* src = Whh + ((size_t)(g * 256 + c * 64 + u)) * 256;
        __nv_bfloat16* whi = (__nv_bfloat16*)(smr + STG_B) + tid * WSTR;
        __nv_bfloat16* wlo = (__nv_bfloat16*)(smr + WLO_B) + tid * WSTR;
#pragma unroll 4
        for (int q = 0; q < 64; q++) {
            __nv_bfloat162 h0, h1, l0, l1;
            split4(*(const float4*)(src + q * 4), h0, h1, l0, l1);
            *(__nv_bfloat162*)(whi + q * 4)     = h0;
            *(__nv_bfloat162*)(whi + q * 4 + 2) = h1;
            *(__nv_bfloat162*)(wlo + q * 4)     = l0;
            *(__nv_bfloat162*)(wlo + q * 4 + 2) = l1;
        }
    }
    __syncthreads();

    // ---- preload W-hi fragments into registers (warp wid: n-tiles 2wid,2wid+1)
    const int tn0 = wid * 2;
    uint32_t bhi[2][16][2];
    {
#pragma unroll
        for (int nt = 0; nt < 2; nt++) {
            const uint32_t base = sb + STG_B
                + 2u * (((tn0 + nt) * 8 + (lane & 7)) * WSTR + ((lane >> 3) & 1) * 8);
#pragma unroll
            for (int ks = 0; ks < 16; ks++)
                ldsm_x2(bhi[nt][ks], base + (uint32_t)(ks * 32));
        }
    }
    __syncthreads();   // all fragment reads done before staging is reused

    // zero both h buffers (hi+lo x2 = 33792 B = 8448 words)
    for (int i = tid; i < 8448; i += KR_THREADS) ((uint32_t*)(smr + HH0_B))[i] = 0;
    __syncthreads();
    cluster_sync_();   // peers' h buffers zeroed before any remote store

    // ---- per-buffer phase-A h fragment addresses -------------------------
    const uint32_t hfo = 2u * ((lane & 15) * WSTR + (lane >> 4) * 8);
    const uint32_t aHiP[2] = { sb + HH0_B + hfo, sb + HH1_B + hfo };
    // W-lo fragment addresses (persistent region)
    uint32_t blAd[2];
#pragma unroll
    for (int nt = 0; nt < 2; nt++)
        blAd[nt] = sb + WLO_B + 2u * (((tn0 + nt) * 8 + (lane & 7)) * WSTR + ((lane >> 3) & 1) * 8);

    // ---- phase-B constants (warps 0-7: rows 2*wid, 2*wid+1) --------------
    const bool cellw = (wid < 8);
    const int lu  = lane * 2;
    const int gu  = c * 64 + lu;
    const int row0 = 2 * wid;                       // valid when cellw
    float2 bnv = make_float2(0.f, 0.f);
    const float* ig0 = g_ig;
    const float* ig1 = g_ig;
    if (cellw) {
        bnv = *(const float2*)(bnb + gu);
        ig0 = g_ig + ((size_t)(cl * 16 + row0)) * T_ * G3_ + gu;
        ig1 = ig0 + (size_t)T_ * G3_;
    }
    float* Dm = (float*)(smr + D_B);
    uint32_t pp[4];
#pragma unroll
    for (int r = 0; r < 4; r++) pp[r] = mapa_u32(sb, r);
    const uint32_t ho0 = 2u * (row0 * WSTR + gu);         // + buffer base
    const uint32_t ho1 = 2u * ((row0 + 1) * WSTR + gu);
    const uint32_t hbase[2] = { HH0_B, HH1_B };           // lo = +8448
    float2 hp0 = make_float2(0.f, 0.f), hp1 = make_float2(0.f, 0.f);
    const int grp = lane >> 2, qc = (lane & 3) * 2;

    for (int t = 0; t < T_; t++) {
        const int p  = t & 1;        // read buffer
        const int pw = p ^ 1;        // write buffer

        // prefetch input gates (cell warps only)
        float2 gr0, gz0, gn0, gr1, gz1, gn1;
        if (cellw) {
            const float* q0 = ig0 + (size_t)t * G3_;
            const float* q1 = ig1 + (size_t)t * G3_;
            gr0 = *(const float2*)(q0);
            gz0 = *(const float2*)(q0 + 256);
            gn0 = *(const float2*)(q0 + 512);
            gr1 = *(const float2*)(q1);
            gz1 = *(const float2*)(q1 + 256);
            gn1 = *(const float2*)(q1 + 512);
        }

        // ---- phase A: D = h @ W^T (3 bf16 chains; W-hi from registers) ----
        float a0[4] = {0.f, 0.f, 0.f, 0.f};
        float a1[4] = {0.f, 0.f, 0.f, 0.f};
        const uint32_t aHi = aHiP[p];
        const uint32_t aLo = aHi + 8448u;
#pragma unroll
        for (int ks = 0; ks < 16; ks++) {
            const uint32_t ko = (uint32_t)(ks * 32);
            uint32_t ah[4], al[4];
            ldsm_x4(ah, aHi + ko);
            ldsm_x4(al, aLo + ko);
            uint32_t bl0[2], bl1[2];
            ldsm_x2(bl0, blAd[0] + ko);
            ldsm_x2(bl1, blAd[1] + ko);
            mma_bf16(a0, ah, bhi[0][ks]); mma_bf16(a1, ah, bhi[1][ks]);
            mma_bf16(a0, ah, bl0);        mma_bf16(a1, ah, bl1);
            mma_bf16(a0, al, bhi[0][ks]); mma_bf16(a1, al, bhi[1][ks]);
        }
        // stage D fragments (CTA-local slab): warp wid -> cols [16wid,16wid+16)
        {
            const int col = tn0 * 8 + qc;
            *(float2*)(Dm + grp * DSTR + col)           = make_float2(a0[0], a0[1]);
            *(float2*)(Dm + (grp + 8) * DSTR + col)     = make_float2(a0[2], a0[3]);
            *(float2*)(Dm + grp * DSTR + col + 8)       = make_float2(a1[0], a1[1]);
            *(float2*)(Dm + (grp + 8) * DSTR + col + 8) = make_float2(a1[2], a1[3]);
        }
        __syncthreads();   // D visible CTA-locally

        // ---- phase B: GRU cells + cluster-wide h update (warps 0-7) ------
        if (cellw) {
            const float2 dr0 = *(const float2*)(Dm + row0 * DSTR + lu);
            const float2 dz0 = *(const float2*)(Dm + row0 * DSTR + 64 + lu);
            const float2 dn0 = *(const float2*)(Dm + row0 * DSTR + 128 + lu);
            const float2 dr1 = *(const float2*)(Dm + (row0 + 1) * DSTR + lu);
            const float2 dz1 = *(const float2*)(Dm + (row0 + 1) * DSTR + 64 + lu);
            const float2 dn1 = *(const float2*)(Dm + (row0 + 1) * DSTR + 128 + lu);

            const float h00 = gru_cell(gr0.x, gz0.x, gn0.x, dr0.x, dz0.x, dn0.x, bnv.x, hp0.x);
            const float h01 = gru_cell(gr0.y, gz0.y, gn0.y, dr0.y, dz0.y, dn0.y, bnv.y, hp0.y);
            const float h10 = gru_cell(gr1.x, gz1.x, gn1.x, dr1.x, dz1.x, dn1.x, bnv.x, hp1.x);
            const float h11 = gru_cell(gr1.y, gz1.y, gn1.y, dr1.y, dz1.y, dn1.y, bnv.y, hp1.y);
            hp0 = make_float2(h00, h01);
            hp1 = make_float2(h10, h11);

            __nv_bfloat162 hi0 = __floats2bfloat162_rn(h00, h01);
            __nv_bfloat162 lo0 = __floats2bfloat162_rn(h00 - __bfloat162float(hi0.x),
                                                       h01 - __bfloat162float(hi0.y));
            __nv_bfloat162 hi1 = __floats2bfloat162_rn(h10, h11);
            __nv_bfloat162 lo1 = __floats2bfloat162_rn(h10 - __bfloat162float(hi1.x),
                                                       h11 - __bfloat162float(hi1.y));
            const uint32_t wh0 = *reinterpret_cast<uint32_t*>(&hi0);
            const uint32_t wl0 = *reinterpret_cast<uint32_t*>(&lo0);
            const uint32_t wh1 = *reinterpret_cast<uint32_t*>(&hi1);
            const uint32_t wl1 = *reinterpret_cast<uint32_t*>(&lo1);
            const uint32_t hb = hbase[pw];
#pragma unroll
            for (int r = 0; r < 4; r++) {
                stc_b32(pp[r] + hb + ho0,         wh0);
                stc_b32(pp[r] + hb + ho0 + 8448u, wl0);
                stc_b32(pp[r] + hb + ho1,         wh1);
                stc_b32(pp[r] + hb + ho1 + 8448u, wl1);
            }
        }
        cluster_sync_();   // h_{t+1} visible everywhere; step boundary
    }

    // final h (in registers) -> g_hfin
    if (cellw) {
        *(float2*)(g_hfin + (size_t)(cl * 16 + row0) * H_ + gu)     = hp0;
        *(float2*)(g_hfin + (size_t)(cl * 16 + row0 + 1) * H_ + gu) = hp1;
    }
}

// ---------------------------------------------------------------------------
// Phase 3: out = h_final @ w_lin^T + bias_out   (512 x 128, trivial)
// ---------------------------------------------------------------------------
__global__ void __launch_bounds__(128) k_out(const float* __restrict__ wl,
                                             const float* __restrict__ bo,
                                             float* __restrict__ out)
{
    __shared__ float sh[256];
    const int b = blockIdx.x, o = threadIdx.x;
    sh[o]       = g_hfin[(size_t)b * H_ + o];
    sh[o + 128] = g_hfin[(size_t)b * H_ + o + 128];
    __syncthreads();

    float acc = bo[o];
    const float4* wp = (const float4*)(wl + (size_t)o * H_);
#pragma unroll 8
    for (int q = 0; q < 64; q++) {
        const float4 w = wp[q];
        const float4 h = *(const float4*)(sh + q * 4);
        acc += w.x * h.x + w.y * h.y + w.z * h.z + w.w * h.w;
    }
    out[(size_t)b * OUT_ + o] = acc;
}

// ---------------------------------------------------------------------------
extern "C" void kernel_launch(void* const* d_in, const int* in_sizes, int n_in,
                              void* d_out, int out_size)
{
    (void)in_sizes; (void)n_in; (void)out_size;
    const float* x   = (const float*)d_in[0];  // (B,T,IN)
    const float* wih = (const float*)d_in[1];  // (3H,IN)
    const float* whh = (const float*)d_in[2];  // (3H,H)
    const float* bg  = (const float*)d_in[3];  // (3H)
    const float* bnn = (const float*)d_in[4];  // (H)
    const float* wl  = (const float*)d_in[5];  // (OUT,H)
    const float* bo  = (const float*)d_in[6];  // (OUT)
    float* out = (float*)d_out;                // (B,OUT)

    cudaFuncSetAttribute(k_ih_mma,  cudaFuncAttributeMaxDynamicSharedMemorySize, P1_SMEM_BYTES);
    cudaFuncSetAttribute(k_rec_mma, cudaFuncAttributeMaxDynamicSharedMemorySize, KR_SMEM_BYTES);

    k_ih_mma<<<dim3(G3_ / 128, (B_ * T_) / 128), 256, P1_SMEM_BYTES>>>(x, wih, bg);
    k_rec_mma<<<128, KR_THREADS, KR_SMEM_BYTES>>>(whh, bnn);
    k_out<<<B_, 128>>>(wl, bo, out);
}

// round 16
// speedup vs baseline: 1.2760x; 1.0076x over previous
#include <cuda_runtime.h>
#include <cuda_bf16.h>
#include <cstdint>
#include <math.h>

// Problem dims
#define B_   512
#define T_   512
#define IN_  128
#define H_   256
#define G3_  768   // 3*H
#define OUT_ 128

__device__ float g_ig[(size_t)B_ * T_ * G3_];     // ~805 MB  [B][T][3H]
__device__ float g_hfin[(size_t)B_ * H_];

typedef unsigned long long ull;

// ---------------- generic smem / cluster helpers ---------------------------
__device__ __forceinline__ uint32_t smem_u32(const void* p) {
    uint32_t a;
    asm("{ .reg .u64 t; cvta.to.shared.u64 t, %1; cvt.u32.u64 %0, t; }" : "=r"(a) : "l"(p));
    return a;
}
__device__ __forceinline__ uint32_t mapa_u32(uint32_t a, uint32_t rank) {
    uint32_t r;
    asm("mapa.shared::cluster.u32 %0, %1, %2;" : "=r"(r) : "r"(a), "r"(rank));
    return r;
}
__device__ __forceinline__ void stc_b32(uint32_t a, uint32_t v) {
    asm volatile("st.shared::cluster.u32 [%0], %1;" :: "r"(a), "r"(v) : "memory");
}
__device__ __forceinline__ void cluster_sync_() {
    asm volatile("barrier.cluster.arrive.aligned;" ::: "memory");
    asm volatile("barrier.cluster.wait.aligned;"   ::: "memory");
}

// ---------------- mma.sync helpers (sm_80-era HMMA, valid on sm_100) -------
__device__ __forceinline__ void ldsm_x4(uint32_t* r, uint32_t addr) {
    asm volatile("ldmatrix.sync.aligned.m8n8.x4.shared.b16 {%0,%1,%2,%3}, [%4];"
                 : "=r"(r[0]), "=r"(r[1]), "=r"(r[2]), "=r"(r[3]) : "r"(addr));
}
__device__ __forceinline__ void ldsm_x2(uint32_t* r, uint32_t addr) {
    asm volatile("ldmatrix.sync.aligned.m8n8.x2.shared.b16 {%0,%1}, [%2];"
                 : "=r"(r[0]), "=r"(r[1]) : "r"(addr));
}
__device__ __forceinline__ void mma_bf16(float* d, const uint32_t* a, const uint32_t* b) {
    asm volatile(
        "mma.sync.aligned.m16n8k16.row.col.f32.bf16.bf16.f32 "
        "{%0,%1,%2,%3}, {%4,%5,%6,%7}, {%8,%9}, {%0,%1,%2,%3};"
        : "+f"(d[0]), "+f"(d[1]), "+f"(d[2]), "+f"(d[3])
        : "r"(a[0]), "r"(a[1]), "r"(a[2]), "r"(a[3]), "r"(b[0]), "r"(b[1]));
}

// bf16 hi/lo split of a float4 -> 4 packed bf16x2 (hi pair0, hi pair1, lo0, lo1)
__device__ __forceinline__ void split4(const float4 v,
                                       __nv_bfloat162& h0, __nv_bfloat162& h1,
                                       __nv_bfloat162& l0, __nv_bfloat162& l1) {
    h0 = __floats2bfloat162_rn(v.x, v.y);
    h1 = __floats2bfloat162_rn(v.z, v.w);
    l0 = __floats2bfloat162_rn(v.x - __bfloat162float(h0.x), v.y - __bfloat162float(h0.y));
    l1 = __floats2bfloat162_rn(v.z - __bfloat162float(h1.x), v.w - __bfloat162float(h1.y));
}

// ---------------------------------------------------------------------------
// Phase 1 (HMMA): ig = X @ W_ih^T + bias via bf16-split mma.sync.
// 128x128 CTA tile, 8 warps = 4m x 2n, each warp 32x64 (proven ~815 us).
// ---------------------------------------------------------------------------
#define P1_STR  72
#define AHI_OFF 0
#define ALO_OFF (128 * P1_STR * 2)
#define BHI_OFF (2 * 128 * P1_STR * 2)
#define BLO_OFF (BHI_OFF + 128 * P1_STR * 2)
#define P1_SMEM_BYTES (BLO_OFF + 128 * P1_STR * 2)  // 73728

__global__ void __launch_bounds__(256, 2)
k_ih_mma(const float* __restrict__ X, const float* __restrict__ W,
         const float* __restrict__ bias)
{
    extern __shared__ char smc[];
    const uint32_t sb = smem_u32(smc);
    const int tid  = threadIdx.x;
    const int wid  = tid >> 5, lane = tid & 31;
    const int bn   = blockIdx.x;
    const int bm   = blockIdx.y;

    const int wm = wid & 3;
    const int wn = wid >> 2;

    const uint32_t aHi0 = sb + AHI_OFF + 2u * ((wm * 32 + (lane & 15)) * P1_STR + (lane >> 4) * 8);
    const uint32_t aLo0 = aHi0 + ALO_OFF;
    const uint32_t bHi0 = sb + BHI_OFF + 2u * ((wn * 64 + ((lane >> 4) & 1) * 8 + (lane & 7)) * P1_STR
                                               + ((lane >> 3) & 1) * 8);
    const uint32_t bLo0 = bHi0 + (BLO_OFF - BHI_OFF);

    float acc[2][8][4];
#pragma unroll
    for (int mt = 0; mt < 2; mt++)
#pragma unroll
        for (int nt = 0; nt < 8; nt++)
#pragma unroll
            for (int e = 0; e < 4; e++) acc[mt][nt][e] = 0.f;

    for (int kk = 0; kk < 128; kk += 64) {
        if (kk) __syncthreads();
        {
            const int row = tid >> 1;
            const int kp  = (tid & 1) * 32;
            const float* xs = X + ((size_t)(bm * 128 + row)) * 128 + kk + kp;
            const float* ws = W + ((size_t)(bn * 128 + row)) * 128 + kk + kp;
            __nv_bfloat16* ah = (__nv_bfloat16*)(smc + AHI_OFF) + row * P1_STR + kp;
            __nv_bfloat16* al = (__nv_bfloat16*)(smc + ALO_OFF) + row * P1_STR + kp;
            __nv_bfloat16* bh = (__nv_bfloat16*)(smc + BHI_OFF) + row * P1_STR + kp;
            __nv_bfloat16* bl = (__nv_bfloat16*)(smc + BLO_OFF) + row * P1_STR + kp;
#pragma unroll
            for (int q = 0; q < 8; q++) {
                __nv_bfloat162 h0, h1, l0, l1;
                split4(*(const float4*)(xs + q * 4), h0, h1, l0, l1);
                *(__nv_bfloat162*)(ah + q * 4)     = h0;
                *(__nv_bfloat162*)(ah + q * 4 + 2) = h1;
                *(__nv_bfloat162*)(al + q * 4)     = l0;
                *(__nv_bfloat162*)(al + q * 4 + 2) = l1;
                split4(*(const float4*)(ws + q * 4), h0, h1, l0, l1);
                *(__nv_bfloat162*)(bh + q * 4)     = h0;
                *(__nv_bfloat162*)(bh + q * 4 + 2) = h1;
                *(__nv_bfloat162*)(bl + q * 4)     = l0;
                *(__nv_bfloat162*)(bl + q * 4 + 2) = l1;
            }
        }
        __syncthreads();

#pragma unroll
        for (int ks = 0; ks < 4; ks++) {
            const uint32_t ko = (uint32_t)(ks * 32);
            uint32_t ah[2][4], bh[4][4];
#pragma unroll
            for (int mt = 0; mt < 2; mt++)
                ldsm_x4(ah[mt], aHi0 + (uint32_t)(mt * 16 * P1_STR * 2) + ko);
#pragma unroll
            for (int np = 0; np < 4; np++)
                ldsm_x4(bh[np], bHi0 + (uint32_t)(np * 16 * P1_STR * 2) + ko);
#pragma unroll
            for (int mt = 0; mt < 2; mt++)
#pragma unroll
                for (int nt = 0; nt < 8; nt++)
                    mma_bf16(acc[mt][nt], ah[mt], &bh[nt >> 1][(nt & 1) * 2]);
            {
                uint32_t bl[4][4];
#pragma unroll
                for (int np = 0; np < 4; np++)
                    ldsm_x4(bl[np], bLo0 + (uint32_t)(np * 16 * P1_STR * 2) + ko);
#pragma unroll
                for (int mt = 0; mt < 2; mt++)
#pragma unroll
                    for (int nt = 0; nt < 8; nt++)
                        mma_bf16(acc[mt][nt], ah[mt], &bl[nt >> 1][(nt & 1) * 2]);
            }
            {
                uint32_t al[2][4];
#pragma unroll
                for (int mt = 0; mt < 2; mt++)
                    ldsm_x4(al[mt], aLo0 + (uint32_t)(mt * 16 * P1_STR * 2) + ko);
#pragma unroll
                for (int mt = 0; mt < 2; mt++)
#pragma unroll
                    for (int nt = 0; nt < 8; nt++)
                        mma_bf16(acc[mt][nt], al[mt], &bh[nt >> 1][(nt & 1) * 2]);
            }
        }
    }

    const int grp = lane >> 2;
    const int qc  = (lane & 3) * 2;
#pragma unroll
    for (int mt = 0; mt < 2; mt++) {
        const int r0 = bm * 128 + wm * 32 + mt * 16 + grp;
#pragma unroll
        for (int nt = 0; nt < 8; nt++) {
            const int col = bn * 128 + wn * 64 + nt * 8 + qc;
            const float2 bb = *(const float2*)(bias + col);
            float* d0 = g_ig + (size_t)r0 * G3_ + col;
            float* d1 = d0 + (size_t)8 * G3_;
            *(float2*)d0 = make_float2(acc[mt][nt][0] + bb.x, acc[mt][nt][1] + bb.y);
            *(float2*)d1 = make_float2(acc[mt][nt][2] + bb.x, acc[mt][nt][3] + bb.y);
        }
    }
}

// ---------------------------------------------------------------------------
// Phase 2 (HMMA): GRU recurrence, v4: SPLIT-K, 16 warps (512 thr, 4/SMSP).
// Warps w and w+8 own the same 3 n-tiles with k-halves [0,8) / [8,16):
// total ldsm traffic identical to the best 8-warp config (1792 wf/step) but
// twice the latency-hiding slots. Partial D's in two slabs, summed in phase B.
// W-hi register-resident: 3 tiles x 8 ks x 2 = 48 regs/thread.
// smem: [0,101376) W-lo | [101376,202752) W-hi staging at init, then
//       hHi0/hLo0/hHi1/hLo1 (4 x 8448) + D0/D1 (2 x 12800).
// ---------------------------------------------------------------------------
#define WSTR    264                 // bf16/row (256+8)
#define WLO_B   0
#define STG_B   101376
#define HH0_B   101376
#define HH1_B   118272
#define D_B     135168
#define DSTR    200                 // floats
#define DSLAB_F 3200                // floats per slab (16 x DSTR)
#define KR_SMEM_BYTES 202752
#define KR_THREADS 512

__device__ __forceinline__ float gru_cell(float igr, float igz, float ign,
                                          float ar, float az, float an,
                                          float bnv, float hp) {
    const float r = __fdividef(1.f, 1.f + __expf(-(igr + ar)));
    const float z = __fdividef(1.f, 1.f + __expf(-(igz + az)));
    const float a = ign + r * (an + bnv);
    const float n = __fdividef(2.f, 1.f + __expf(-2.f * a)) - 1.f;
    return n + z * (hp - n);
}

__global__ void __launch_bounds__(KR_THREADS, 1) __cluster_dims__(4, 1, 1)
k_rec_mma(const float* __restrict__ Whh, const float* __restrict__ bnb)
{
    extern __shared__ char smr[];
    const uint32_t sb = smem_u32(smr);
    const int tid = threadIdx.x;
    const int wid = tid >> 5, lane = tid & 31;
    const int c   = blockIdx.x & 3;   // cluster rank (unit chunk)
    const int cl  = blockIdx.x >> 2;  // cluster id: batch rows [cl*16, +16)

    // ---- stage W_hh chunk: hi -> staging region, lo -> persistent region --
    if (tid < 192) {
        const int g = tid >> 6, u = tid & 63;
        const float* src = Whh + ((size_t)(g * 256 + c * 64 + u)) * 256;
        __nv_bfloat16* whi = (__nv_bfloat16*)(smr + STG_B) + tid * WSTR;
        __nv_bfloat16* wlo = (__nv_bfloat16*)(smr + WLO_B) + tid * WSTR;
#pragma unroll 4
        for (int q = 0; q < 64; q++) {
            __nv_bfloat162 h0, h1, l0, l1;
            split4(*(const float4*)(src + q * 4), h0, h1, l0, l1);
            *(__nv_bfloat162*)(whi + q * 4)     = h0;
            *(__nv_bfloat162*)(whi + q * 4 + 2) = h1;
            *(__nv_bfloat162*)(wlo + q * 4)     = l0;
            *(__nv_bfloat162*)(wlo + q * 4 + 2) = l1;
        }
    }
    __syncthreads();

    // ---- warp roles: wln = n-group (3 tiles), kh = k-half -----------------
    const int wln = wid & 7;            // 0..7
    const int kh  = wid >> 3;           // 0..1
    const int tn0 = wln * 3;
    const int ksb = kh * 8;             // ks base

    // ---- preload W-hi fragments for this warp's (tiles, k-half) ----------
    uint32_t bhi[3][8][2];
    {
#pragma unroll
        for (int nt = 0; nt < 3; nt++) {
            const uint32_t base = sb + STG_B
                + 2u * (((tn0 + nt) * 8 + (lane & 7)) * WSTR + ((lane >> 3) & 1) * 8);
#pragma unroll
            for (int ks = 0; ks < 8; ks++)
                ldsm_x2(bhi[nt][ks], base + (uint32_t)((ksb + ks) * 32));
        }
    }
    __syncthreads();   // all fragment reads done before staging is reused

    // zero both h buffers (hi+lo x2 = 33792 B = 8448 words)
    for (int i = tid; i < 8448; i += KR_THREADS) ((uint32_t*)(smr + HH0_B))[i] = 0;
    __syncthreads();
    cluster_sync_();   // peers' h buffers zeroed before any remote store

    // ---- per-buffer phase-A h fragment addresses -------------------------
    const uint32_t hfo = 2u * ((lane & 15) * WSTR + (lane >> 4) * 8);
    const uint32_t aHiP[2] = { sb + HH0_B + hfo, sb + HH1_B + hfo };
    // W-lo fragment addresses (persistent region)
    uint32_t blAd[3];
#pragma unroll
    for (int nt = 0; nt < 3; nt++)
        blAd[nt] = sb + WLO_B + 2u * (((tn0 + nt) * 8 + (lane & 7)) * WSTR + ((lane >> 3) & 1) * 8);

    // ---- phase-B constants (warps 0-7: rows 2*wid, 2*wid+1) --------------
    const bool cellw = (wid < 8);
    const int lu  = lane * 2;
    const int gu  = c * 64 + lu;
    const int row0 = 2 * wid;                       // valid when cellw
    float2 bnv = make_float2(0.f, 0.f);
    const float* ig0 = g_ig;
    const float* ig1 = g_ig;
    if (cellw) {
        bnv = *(const float2*)(bnb + gu);
        ig0 = g_ig + ((size_t)(cl * 16 + row0)) * T_ * G3_ + gu;
        ig1 = ig0 + (size_t)T_ * G3_;
    }
    float* Dm0 = (float*)(smr + D_B);
    float* Dmk = Dm0 + kh * DSLAB_F;     // this warp's output slab
    uint32_t pp[4];
#pragma unroll
    for (int r = 0; r < 4; r++) pp[r] = mapa_u32(sb, r);
    const uint32_t ho0 = 2u * (row0 * WSTR + gu);         // + buffer base
    const uint32_t ho1 = 2u * ((row0 + 1) * WSTR + gu);
    const uint32_t hbase[2] = { HH0_B, HH1_B };           // lo = +8448
    float2 hp0 = make_float2(0.f, 0.f), hp1 = make_float2(0.f, 0.f);
    const int grp = lane >> 2, qc = (lane & 3) * 2;

    for (int t = 0; t < T_; t++) {
        const int p  = t & 1;        // read buffer
        const int pw = p ^ 1;        // write buffer

        // prefetch input gates (cell warps only)
        float2 gr0, gz0, gn0, gr1, gz1, gn1;
        if (cellw) {
            const float* q0 = ig0 + (size_t)t * G3_;
            const float* q1 = ig1 + (size_t)t * G3_;
            gr0 = *(const float2*)(q0);
            gz0 = *(const float2*)(q0 + 256);
            gn0 = *(const float2*)(q0 + 512);
            gr1 = *(const float2*)(q1);
            gz1 = *(const float2*)(q1 + 256);
            gn1 = *(const float2*)(q1 + 512);
        }

        // ---- phase A: partial D = h @ W^T over this warp's k-half --------
        float a0[4] = {0.f, 0.f, 0.f, 0.f};
        float a1[4] = {0.f, 0.f, 0.f, 0.f};
        float a2[4] = {0.f, 0.f, 0.f, 0.f};
        const uint32_t aHi = aHiP[p];
        const uint32_t aLo = aHi + 8448u;
#pragma unroll
        for (int ks = 0; ks < 8; ks++) {
            const uint32_t ko = (uint32_t)((ksb + ks) * 32);
            uint32_t ah[4], al[4];
            ldsm_x4(ah, aHi + ko);
            ldsm_x4(al, aLo + ko);
            uint32_t bl0[2], bl1[2], bl2[2];
            ldsm_x2(bl0, blAd[0] + ko);
            ldsm_x2(bl1, blAd[1] + ko);
            ldsm_x2(bl2, blAd[2] + ko);
            mma_bf16(a0, ah, bhi[0][ks]); mma_bf16(a1, ah, bhi[1][ks]); mma_bf16(a2, ah, bhi[2][ks]);
            mma_bf16(a0, ah, bl0);        mma_bf16(a1, ah, bl1);        mma_bf16(a2, ah, bl2);
            mma_bf16(a0, al, bhi[0][ks]); mma_bf16(a1, al, bhi[1][ks]); mma_bf16(a2, al, bhi[2][ks]);
        }
        // stage partial D fragments into this k-half's slab
        {
            const int col = tn0 * 8 + qc;
            *(float2*)(Dmk + grp * DSTR + col)            = make_float2(a0[0], a0[1]);
            *(float2*)(Dmk + (grp + 8) * DSTR + col)      = make_float2(a0[2], a0[3]);
            *(float2*)(Dmk + grp * DSTR + col + 8)        = make_float2(a1[0], a1[1]);
            *(float2*)(Dmk + (grp + 8) * DSTR + col + 8)  = make_float2(a1[2], a1[3]);
            *(float2*)(Dmk + grp * DSTR + col + 16)       = make_float2(a2[0], a2[1]);
            *(float2*)(Dmk + (grp + 8) * DSTR + col + 16) = make_float2(a2[2], a2[3]);
        }
        __syncthreads();   // both slabs visible CTA-locally

        // ---- phase B: GRU cells + cluster-wide h update (warps 0-7) ------
        if (cellw) {
            const float* Dr = Dm0 + row0 * DSTR;
            const float* Ds = Dr + DSLAB_F;
            const float2 dr0a = *(const float2*)(Dr + lu);
            const float2 dz0a = *(const float2*)(Dr + 64 + lu);
            const float2 dn0a = *(const float2*)(Dr + 128 + lu);
            const float2 dr1a = *(const float2*)(Dr + DSTR + lu);
            const float2 dz1a = *(const float2*)(Dr + DSTR + 64 + lu);
            const float2 dn1a = *(const float2*)(Dr + DSTR + 128 + lu);
            const float2 dr0b = *(const float2*)(Ds + lu);
            const float2 dz0b = *(const float2*)(Ds + 64 + lu);
            const float2 dn0b = *(const float2*)(Ds + 128 + lu);
            const float2 dr1b = *(const float2*)(Ds + DSTR + lu);
            const float2 dz1b = *(const float2*)(Ds + DSTR + 64 + lu);
            const float2 dn1b = *(const float2*)(Ds + DSTR + 128 + lu);

            const float h00 = gru_cell(gr0.x, gz0.x, gn0.x, dr0a.x + dr0b.x, dz0a.x + dz0b.x,
                                       dn0a.x + dn0b.x, bnv.x, hp0.x);
            const float h01 = gru_cell(gr0.y, gz0.y, gn0.y, dr0a.y + dr0b.y, dz0a.y + dz0b.y,
                                       dn0a.y + dn0b.y, bnv.y, hp0.y);
            const float h10 = gru_cell(gr1.x, gz1.x, gn1.x, dr1a.x + dr1b.x, dz1a.x + dz1b.x,
                                       dn1a.x + dn1b.x, bnv.x, hp1.x);
            const float h11 = gru_cell(gr1.y, gz1.y, gn1.y, dr1a.y + dr1b.y, dz1a.y + dz1b.y,
                                       dn1a.y + dn1b.y, bnv.y, hp1.y);
            hp0 = make_float2(h00, h01);
            hp1 = make_float2(h10, h11);

            __nv_bfloat162 hi0 = __floats2bfloat162_rn(h00, h01);
            __nv_bfloat162 lo0 = __floats2bfloat162_rn(h00 - __bfloat162float(hi0.x),
                                                       h01 - __bfloat162float(hi0.y));
            __nv_bfloat162 hi1 = __floats2bfloat162_rn(h10, h11);
            __nv_bfloat162 lo1 = __floats2bfloat162_rn(h10 - __bfloat162float(hi1.x),
                                                       h11 - __bfloat162float(hi1.y));
            const uint32_t wh0 = *reinterpret_cast<uint32_t*>(&hi0);
            const uint32_t wl0 = *reinterpret_cast<uint32_t*>(&lo0);
            const uint32_t wh1 = *reinterpret_cast<uint32_t*>(&hi1);
            const uint32_t wl1 = *reinterpret_cast<uint32_t*>(&lo1);
            const uint32_t hb = hbase[pw];
#pragma unroll
            for (int r = 0; r < 4; r++) {
                stc_b32(pp[r] + hb + ho0,         wh0);
                stc_b32(pp[r] + hb + ho0 + 8448u, wl0);
                stc_b32(pp[r] + hb + ho1,         wh1);
                stc_b32(pp[r] + hb + ho1 + 8448u, wl1);
            }
        }
        cluster_sync_();   // h_{t+1} visible everywhere; step boundary
    }

    // final h (in registers) -> g_hfin
    if (cellw) {
        *(float2*)(g_hfin + (size_t)(cl * 16 + row0) * H_ + gu)     = hp0;
        *(float2*)(g_hfin + (size_t)(cl * 16 + row0 + 1) * H_ + gu) = hp1;
    }
}

// ---------------------------------------------------------------------------
// Phase 3: out = h_final @ w_lin^T + bias_out   (512 x 128, trivial)
// ---------------------------------------------------------------------------
__global__ void __launch_bounds__(128) k_out(const float* __restrict__ wl,
                                             const float* __restrict__ bo,
                                             float* __restrict__ out)
{
    __shared__ float sh[256];
    const int b = blockIdx.x, o = threadIdx.x;
    sh[o]       = g_hfin[(size_t)b * H_ + o];
    sh[o + 128] = g_hfin[(size_t)b * H_ + o + 128];
    __syncthreads();

    float acc = bo[o];
    const float4* wp = (const float4*)(wl + (size_t)o * H_);
#pragma unroll 8
    for (int q = 0; q < 64; q++) {
        const float4 w = wp[q];
        const float4 h = *(const float4*)(sh + q * 4);
        acc += w.x * h.x + w.y * h.y + w.z * h.z + w.w * h.w;
    }
    out[(size_t)b * OUT_ + o] = acc;
}

// ---------------------------------------------------------------------------
extern "C" void kernel_launch(void* const* d_in, const int* in_sizes, int n_in,
                              void* d_out, int out_size)
{
    (void)in_sizes; (void)n_in; (void)out_size;
    const float* x   = (const float*)d_in[0];  // (B,T,IN)
    const float* wih = (const float*)d_in[1];  // (3H,IN)
    const float* whh = (const float*)d_in[2];  // (3H,H)
    const float* bg  = (const float*)d_in[3];  // (3H)
    const float* bnn = (const float*)d_in[4];  // (H)
    const float* wl  = (const float*)d_in[5];  // (OUT,H)
    const float* bo  = (const float*)d_in[6];  // (OUT)
    float* out = (float*)d_out;                // (B,OUT)

    cudaFuncSetAttribute(k_ih_mma,  cudaFuncAttributeMaxDynamicSharedMemorySize, P1_SMEM_BYTES);
    cudaFuncSetAttribute(k_rec_mma, cudaFuncAttributeMaxDynamicSharedMemorySize, KR_SMEM_BYTES);

    k_ih_mma<<<dim3(G3_ / 128, (B_ * T_) / 128), 256, P1_SMEM_BYTES>>>(x, wih, bg);
    k_rec_mma<<<128, KR_THREADS, KR_SMEM_BYTES>>>(whh, bnn);
    k_out<<<B_, 128>>>(wl, bo, out);
}